// round 13
// baseline (speedup 1.0000x reference)
#include <cuda_runtime.h>
#include <cuda_fp16.h>
#include <cstdint>
#include <math.h>

// ============================================================================
// Aligner: out = softmax((ix@W^T+b) @ (io@W^T+b)^T) @ io
// B=8, L=2048, D=1024, fp32 in/out.
// Round 13: cross terms (hi*lo + lo*hi) computed with f16-ACCUMULATOR MMAs
// (chained pair, zero-init per k-step, FFMA drain x 2^-11 into f32 acc).
// Tests the "f32-acc mma.sync is half-rate" hypothesis. lo arrays store
// residual x2048 so f16 operands/products are O(1).
// Pipeline unchanged from R12: streams overlap prep, split-K M, fused io prep.
// ============================================================================

#define BATCH 8
#define LSEQ  2048
#define DIM   1024
#define MELEMS ((size_t)BATCH * LSEQ * DIM)
#define SELEMS ((size_t)BATCH * LSEQ * LSEQ)

#define LO_SC   2048.f
#define INV_SC  (1.f / 2048.f)

// ---- scratch (__device__ globals per allocation rules) ----
__device__ __half g_ix_hi[MELEMS],  g_ix_lo[MELEMS];
__device__ __half g_io_hi[MELEMS],  g_io_lo[MELEMS];
__device__ __half g_ioT_hi[MELEMS];
__device__ __half g_t_hi[MELEMS],   g_t_lo[MELEMS];
__device__ __half g_wt_hi[DIM * DIM], g_wt_lo[DIM * DIM];
__device__ __half g_m_hi[DIM * DIM],  g_m_lo[DIM * DIM];
__device__ float  g_s[SELEMS];                 // scores; head reused as M partials
__device__ __half g_p_hi[SELEMS];
__device__ float  g_p_vec[DIM];
__device__ float  g_r[(size_t)BATCH * LSEQ];

// ============================================================================
// PTX helpers (portable only)
// ============================================================================
__device__ __forceinline__ uint32_t smem_u32(const void* p) {
    uint32_t a;
    asm("{ .reg .u64 t; cvta.to.shared.u64 t, %1; cvt.u32.u64 %0, t; }"
        : "=r"(a) : "l"(p));
    return a;
}

#define CP_COMMIT() asm volatile("cp.async.commit_group;" ::: "memory")
#define CP_WAIT(N)  asm volatile("cp.async.wait_group %0;" :: "n"(N) : "memory")

__device__ __forceinline__ void cp16(uint32_t dst, const void* src) {
    asm volatile("cp.async.cg.shared.global [%0], [%1], 16;" :: "r"(dst), "l"(src));
}

__device__ __forceinline__ void ldsm4(uint32_t* r, uint32_t addr) {
    asm volatile("ldmatrix.sync.aligned.m8n8.x4.shared.b16 {%0,%1,%2,%3}, [%4];"
                 : "=r"(r[0]), "=r"(r[1]), "=r"(r[2]), "=r"(r[3]) : "r"(addr));
}

// f32-accumulator fp16 MMA
__device__ __forceinline__ void mma16816(float* d, const uint32_t* a,
                                         const uint32_t* b) {
    asm volatile(
        "mma.sync.aligned.m16n8k16.row.col.f32.f16.f16.f32 "
        "{%0,%1,%2,%3}, {%4,%5,%6,%7}, {%8,%9}, {%0,%1,%2,%3};"
        : "+f"(d[0]), "+f"(d[1]), "+f"(d[2]), "+f"(d[3])
        : "r"(a[0]), "r"(a[1]), "r"(a[2]), "r"(a[3]), "r"(b[0]), "r"(b[1]));
}

// f16-accumulator fp16 MMA: d(2 regs f16x2) = a*b + c
__device__ __forceinline__ void mma16816h(uint32_t* d, const uint32_t* a,
                                          const uint32_t* b, const uint32_t* c) {
    asm volatile(
        "mma.sync.aligned.m16n8k16.row.col.f16.f16.f16.f16 "
        "{%0,%1}, {%2,%3,%4,%5}, {%6,%7}, {%8,%9};"
        : "=r"(d[0]), "=r"(d[1])
        : "r"(a[0]), "r"(a[1]), "r"(a[2]), "r"(a[3]),
          "r"(b[0]), "r"(b[1]), "r"(c[0]), "r"(c[1]));
}

// tile layout: [rows][64 bytes], 16B chunks swizzled: chunk ^ ((row>>1)&3)
__device__ __forceinline__ uint32_t tile_addr(uint32_t base, int row, int chunk) {
    return base + row * 64 + ((chunk ^ ((row >> 1) & 3)) << 4);
}

// ============================================================================
// Helper kernels  (lo outputs are residual x 2048)
// ============================================================================
__device__ __forceinline__ void split1s(float v, __half& h, __half& l) {
    h = __float2half(v);
    l = __float2half((v - __half2float(h)) * LO_SC);
}

__global__ void split_f32(const float* __restrict__ s,
                          __half* __restrict__ hi,
                          __half* __restrict__ lo, size_t n) {
    size_t i = ((size_t)blockIdx.x * blockDim.x + threadIdx.x) * 4;
    if (i >= n) return;
    float4 v = *(const float4*)(s + i);
    __half h0, h1, h2, h3, l0, l1, l2, l3;
    split1s(v.x, h0, l0); split1s(v.y, h1, l1);
    split1s(v.z, h2, l2); split1s(v.w, h3, l3);
    *(__half2*)(hi + i)     = __halves2half2(h0, h1);
    *(__half2*)(hi + i + 2) = __halves2half2(h2, h3);
    *(__half2*)(lo + i)     = __halves2half2(l0, l1);
    *(__half2*)(lo + i + 2) = __halves2half2(l2, l3);
}

// fused io prep: reads io once; writes io_hi/io_lo (lo x2048) and ioT_hi.
__global__ void prep_io(const float* __restrict__ src,
                        __half* __restrict__ hi, __half* __restrict__ lo,
                        __half* __restrict__ hiT) {
    __shared__ float t[32][33];
    int b = blockIdx.z;
    int l0 = blockIdx.x * 32, d0 = blockIdx.y * 32;
    const float* s = src + (size_t)b * LSEQ * DIM;
    __half* hb = hi + (size_t)b * LSEQ * DIM;
    __half* lb = lo + (size_t)b * LSEQ * DIM;
    #pragma unroll
    for (int i = 0; i < 32; i += 8) {
        float v = s[(size_t)(l0 + threadIdx.y + i) * DIM + d0 + threadIdx.x];
        t[threadIdx.y + i][threadIdx.x] = v;
        __half h, l;
        split1s(v, h, l);
        size_t o = (size_t)(l0 + threadIdx.y + i) * DIM + d0 + threadIdx.x;
        hb[o] = h;
        lb[o] = l;
    }
    __syncthreads();
    size_t ob = (size_t)b * DIM * LSEQ;
    #pragma unroll
    for (int i = 0; i < 32; i += 8) {
        float v = t[threadIdx.x][threadIdx.y + i];
        hiT[ob + (size_t)(d0 + threadIdx.y + i) * LSEQ + l0 + threadIdx.x] =
            __float2half(v);
    }
}

// W transpose + split
__global__ void transpose_split(const float* __restrict__ src,
                                __half* __restrict__ hiT,
                                __half* __restrict__ loT,
                                int rows, int cols) {
    __shared__ float t[32][33];
    int r0 = blockIdx.x * 32, c0 = blockIdx.y * 32;
    #pragma unroll
    for (int i = 0; i < 32; i += 8)
        t[threadIdx.y + i][threadIdx.x] =
            src[(size_t)(r0 + threadIdx.y + i) * cols + c0 + threadIdx.x];
    __syncthreads();
    #pragma unroll
    for (int i = 0; i < 32; i += 8) {
        float v = t[threadIdx.x][threadIdx.y + i];
        __half h, l;
        split1s(v, h, l);
        size_t o = (size_t)(c0 + threadIdx.y + i) * rows + r0 + threadIdx.x;
        hiT[o] = h;
        if (loT) loT[o] = l;
    }
}

// combine 4 fp32 split-K partials of M -> fp16 hi/lo (lo x2048)
__global__ void combine_m(const float* __restrict__ parts,
                          __half* __restrict__ hi, __half* __restrict__ lo) {
    size_t i = ((size_t)blockIdx.x * blockDim.x + threadIdx.x) * 4;
    const size_t stride = (size_t)DIM * DIM;
    float4 a = *(const float4*)(parts + i);
    float4 b = *(const float4*)(parts + stride + i);
    float4 c = *(const float4*)(parts + 2 * stride + i);
    float4 d = *(const float4*)(parts + 3 * stride + i);
    float s0 = a.x + b.x + c.x + d.x;
    float s1 = a.y + b.y + c.y + d.y;
    float s2 = a.z + b.z + c.z + d.z;
    float s3 = a.w + b.w + c.w + d.w;
    __half h0, h1, h2, h3, l0, l1, l2, l3;
    split1s(s0, h0, l0); split1s(s1, h1, l1);
    split1s(s2, h2, l2); split1s(s3, h3, l3);
    *(__half2*)(hi + i)     = __halves2half2(h0, h1);
    *(__half2*)(hi + i + 2) = __halves2half2(h2, h3);
    *(__half2*)(lo + i)     = __halves2half2(l0, l1);
    *(__half2*)(lo + i + 2) = __halves2half2(l2, l3);
}

// p[i] = sum_k b[k] * W[k,i]
__global__ void compute_p(const float* __restrict__ W,
                          const float* __restrict__ b,
                          float* __restrict__ p) {
    int i = blockIdx.x * 128 + threadIdx.x;
    float acc = 0.f;
    for (int k = 0; k < DIM; ++k)
        acc += b[k] * W[(size_t)k * DIM + i];
    p[i] = acc;
}

// r[row] = io[row,:]·p
__global__ void compute_r(const float* __restrict__ io,
                          const float* __restrict__ p,
                          float* __restrict__ r) {
    int row  = blockIdx.x * 8 + (threadIdx.x >> 5);
    int lane = threadIdx.x & 31;
    const float* src = io + (size_t)row * DIM;
    float acc = 0.f;
    for (int d = lane * 4; d < DIM; d += 128) {
        float4 v  = *(const float4*)(src + d);
        float4 pv = *(const float4*)(p + d);
        acc += v.x * pv.x + v.y * pv.y + v.z * pv.z + v.w * pv.w;
    }
    #pragma unroll
    for (int o = 16; o; o >>= 1)
        acc += __shfl_xor_sync(0xFFFFFFFFu, acc, o);
    if (lane == 0) r[row] = acc;
}

// row softmax of (S[row,:] + r[b,:]); writes fp16 hi probabilities
__global__ void softmax_h(float* __restrict__ S,
                          const float* __restrict__ r,
                          __half* __restrict__ phi, int cols) {
    float* row = S + (size_t)blockIdx.x * cols;
    const float* rr = r + (size_t)(blockIdx.x / LSEQ) * LSEQ;
    __half* hr = phi + (size_t)blockIdx.x * cols;
    const int tid = threadIdx.x;

    float lmax = -3.0e38f;
    for (int i = tid * 4; i < cols; i += 1024) {
        float4 v = *(const float4*)(row + i);
        float4 a = *(const float4*)(rr + i);
        v.x += a.x; v.y += a.y; v.z += a.z; v.w += a.w;
        lmax = fmaxf(lmax, fmaxf(fmaxf(v.x, v.y), fmaxf(v.z, v.w)));
    }
    #pragma unroll
    for (int o = 16; o; o >>= 1)
        lmax = fmaxf(lmax, __shfl_xor_sync(0xFFFFFFFFu, lmax, o));
    __shared__ float sm[8], ss[8];
    if ((tid & 31) == 0) sm[tid >> 5] = lmax;
    __syncthreads();
    float rmax = fmaxf(fmaxf(fmaxf(sm[0], sm[1]), fmaxf(sm[2], sm[3])),
                       fmaxf(fmaxf(sm[4], sm[5]), fmaxf(sm[6], sm[7])));

    float lsum = 0.f;
    for (int i = tid * 4; i < cols; i += 1024) {
        float4 v = *(const float4*)(row + i);
        float4 a = *(const float4*)(rr + i);
        v.x = expf(v.x + a.x - rmax); v.y = expf(v.y + a.y - rmax);
        v.z = expf(v.z + a.z - rmax); v.w = expf(v.w + a.w - rmax);
        *(float4*)(row + i) = v;
        lsum += v.x + v.y + v.z + v.w;
    }
    #pragma unroll
    for (int o = 16; o; o >>= 1)
        lsum += __shfl_xor_sync(0xFFFFFFFFu, lsum, o);
    if ((tid & 31) == 0) ss[tid >> 5] = lsum;
    __syncthreads();
    float inv = 1.f / (ss[0]+ss[1]+ss[2]+ss[3]+ss[4]+ss[5]+ss[6]+ss[7]);

    for (int i = tid * 4; i < cols; i += 1024) {
        float4 v = *(const float4*)(row + i);
        __half h0 = __float2half(v.x * inv);
        __half h1 = __float2half(v.y * inv);
        __half h2 = __float2half(v.z * inv);
        __half h3 = __float2half(v.w * inv);
        *(__half2*)(hr + i)     = __halves2half2(h0, h1);
        *(__half2*)(hr + i + 2) = __halves2half2(h2, h3);
    }
}

// ============================================================================
// Split-precision HMMA GEMM, CTA 128x128, warp 64x32, K-chunk 32, 3 stages,
// 2 CTAs/SM. lda/ldb in elements (split-K support).
// NPASS=3: f32-acc hi*hi + f16-acc chained (hi*lo' + lo'*hi), FFMA drain /2048.
// NPASS=1: f32-acc hi*hi only.
// ============================================================================
#define BKC 32
#define TILE_B 8192

template<int NPASS>
__global__ __launch_bounds__(256, 2)
void gemm_split(const __half* __restrict__ Ahi, const __half* __restrict__ Alo,
                const __half* __restrict__ Bhi, const __half* __restrict__ Blo,
                float* __restrict__ Cf,
                __half* __restrict__ Chi, __half* __restrict__ Clo,
                int K, int N, int lda, int ldb,
                long long sA, long long sB, long long sC)
{
    constexpr int NT = (NPASS == 3) ? 4 : 2;
    constexpr int STAGE_B = NT * TILE_B;
    constexpr int NSTAGE = 3;

    extern __shared__ __align__(128) char smem[];
    const uint32_t sb = smem_u32(smem);

    const int tid  = threadIdx.x;
    const int wid  = tid >> 5;
    const int lane = tid & 31;
    const int wm   = wid >> 2;
    const int wn   = wid & 3;

    const long long bz = blockIdx.z;
    const long long m0 = (long long)blockIdx.y * 128;
    const long long n0 = (long long)blockIdx.x * 128;

    const __half* srcs[4];
    int lds[4];
    srcs[0] = Ahi + bz * sA + m0 * lda; lds[0] = lda;
    if (NPASS == 3) {
        srcs[1] = Alo + bz * sA + m0 * lda; lds[1] = lda;
        srcs[2] = Bhi + bz * sB + n0 * ldb; lds[2] = ldb;
        srcs[3] = Blo + bz * sB + n0 * ldb; lds[3] = ldb;
    } else {
        srcs[1] = Bhi + bz * sB + n0 * ldb; lds[1] = ldb;
        srcs[2] = nullptr; lds[2] = 0;
        srcs[3] = nullptr; lds[3] = 0;
    }

    auto load_chunk = [&](int stage, int k0) {
        const uint32_t base = sb + stage * STAGE_B;
        #pragma unroll
        for (int t = 0; t < NT; ++t) {
            #pragma unroll
            for (int j = 0; j < 2; ++j) {
                int idx = tid * 2 + j;
                int row = idx >> 2;
                int ch  = idx & 3;
                cp16(tile_addr(base + t * TILE_B, row, ch),
                     srcs[t] + (long long)row * lds[t] + k0 + ch * 8);
            }
        }
        CP_COMMIT();
    };

    float acc[4][4][4];
    #pragma unroll
    for (int i = 0; i < 4; ++i)
        #pragma unroll
        for (int j = 0; j < 4; ++j)
            #pragma unroll
            for (int e = 0; e < 4; ++e) acc[i][j][e] = 0.f;

    const int NC = K >> 5;
    load_chunk(0, 0);
    load_chunk(1, BKC);

    const int lrow = lane & 15;
    const int lch  = lane >> 4;

    for (int c = 0; c < NC; ++c) {
        if (c + 1 < NC) CP_WAIT(1); else CP_WAIT(0);
        __syncthreads();
        if (c + 2 < NC) load_chunk((c + 2) % NSTAGE, (c + 2) * BKC);

        const uint32_t st  = sb + (c % NSTAGE) * STAGE_B;
        const uint32_t sAh = st;
        const uint32_t sAl = st + TILE_B;
        const uint32_t sBh = st + ((NPASS == 3) ? 2 : 1) * TILE_B;
        const uint32_t sBl = st + 3 * TILE_B;

        #pragma unroll
        for (int ks = 0; ks < 2; ++ks) {
            const int chunk = ks * 2 + lch;
            uint32_t ahi[4][4], alo[4][4];
            uint32_t bhi[4][2], blo[4][2];

            #pragma unroll
            for (int mi = 0; mi < 4; ++mi) {
                const int row = wm * 64 + mi * 16 + lrow;
                ldsm4(ahi[mi], tile_addr(sAh, row, chunk));
                if (NPASS == 3)
                    ldsm4(alo[mi], tile_addr(sAl, row, chunk));
            }
            #pragma unroll
            for (int bi = 0; bi < 2; ++bi) {
                const int row = wn * 32 + bi * 16 + lrow;
                uint32_t t4[4];
                ldsm4(t4, tile_addr(sBh, row, chunk));
                bhi[bi*2][0]   = t4[0]; bhi[bi*2][1]   = t4[2];
                bhi[bi*2+1][0] = t4[1]; bhi[bi*2+1][1] = t4[3];
                if (NPASS == 3) {
                    ldsm4(t4, tile_addr(sBl, row, chunk));
                    blo[bi*2][0]   = t4[0]; blo[bi*2][1]   = t4[2];
                    blo[bi*2+1][0] = t4[1]; blo[bi*2+1][1] = t4[3];
                }
            }

            #pragma unroll
            for (int mi = 0; mi < 4; ++mi)
                #pragma unroll
                for (int ni = 0; ni < 4; ++ni) {
                    mma16816(acc[mi][ni], ahi[mi], bhi[ni]);   // f32-acc hi*hi
                    if (NPASS == 3) {
                        // cross terms: f16-acc chained pair, then drain
                        uint32_t z[2] = {0u, 0u};
                        uint32_t d16[2];
                        mma16816h(d16, ahi[mi], blo[ni], z);
                        mma16816h(d16, alo[mi], bhi[ni], d16);
                        float2 f0 = __half22float2(*(__half2*)&d16[0]);
                        float2 f1 = __half22float2(*(__half2*)&d16[1]);
                        acc[mi][ni][0] = fmaf(f0.x, INV_SC, acc[mi][ni][0]);
                        acc[mi][ni][1] = fmaf(f0.y, INV_SC, acc[mi][ni][1]);
                        acc[mi][ni][2] = fmaf(f1.x, INV_SC, acc[mi][ni][2]);
                        acc[mi][ni][3] = fmaf(f1.y, INV_SC, acc[mi][ni][3]);
                    }
                }
        }
        __syncthreads();
    }

    // ---- epilogue ----
    const int r1 = lane >> 2;
    const int c0 = (lane & 3) * 2;
    #pragma unroll
    for (int mi = 0; mi < 4; ++mi) {
        #pragma unroll
        for (int ni = 0; ni < 4; ++ni) {
            const long long gm = m0 + wm * 64 + mi * 16 + r1;
            const long long gn = n0 + wn * 32 + ni * 8 + c0;
            float v0 = acc[mi][ni][0], v1 = acc[mi][ni][1];
            float v2 = acc[mi][ni][2], v3 = acc[mi][ni][3];
            if (Cf) {
                float* d0 = Cf + bz * sC + gm * N + gn;
                float* d1 = Cf + bz * sC + (gm + 8) * N + gn;
                d0[0] = v0; d0[1] = v1;
                d1[0] = v2; d1[1] = v3;
            } else {
                __half h0, h1, h2, h3, l0, l1, l2, l3;
                split1s(v0, h0, l0); split1s(v1, h1, l1);
                split1s(v2, h2, l2); split1s(v3, h3, l3);
                *(__half2*)(Chi + bz * sC + gm * N + gn)       = __halves2half2(h0, h1);
                *(__half2*)(Clo + bz * sC + gm * N + gn)       = __halves2half2(l0, l1);
                *(__half2*)(Chi + bz * sC + (gm + 8) * N + gn) = __halves2half2(h2, h3);
                *(__half2*)(Clo + bz * sC + (gm + 8) * N + gn) = __halves2half2(l2, l3);
            }
        }
    }
}

// ============================================================================
extern "C" void kernel_launch(void* const* d_in, const int* in_sizes, int n_in,
                              void* d_out, int out_size)
{
    const float* ix = (const float*)d_in[0];
    const float* io = (const float*)d_in[1];
    const float* W  = (const float*)d_in[2];
    const float* bb = (const float*)d_in[3];
    float* out = (float*)d_out;

    __half *ix_hi, *ix_lo, *io_hi, *io_lo, *ioT_hi;
    __half *t_hi, *t_lo, *wt_hi, *wt_lo, *m_hi, *m_lo, *p_hi;
    float *s, *pv, *rv;
    cudaGetSymbolAddress((void**)&ix_hi, g_ix_hi);
    cudaGetSymbolAddress((void**)&ix_lo, g_ix_lo);
    cudaGetSymbolAddress((void**)&io_hi, g_io_hi);
    cudaGetSymbolAddress((void**)&io_lo, g_io_lo);
    cudaGetSymbolAddress((void**)&ioT_hi, g_ioT_hi);
    cudaGetSymbolAddress((void**)&t_hi, g_t_hi);
    cudaGetSymbolAddress((void**)&t_lo, g_t_lo);
    cudaGetSymbolAddress((void**)&wt_hi, g_wt_hi);
    cudaGetSymbolAddress((void**)&wt_lo, g_wt_lo);
    cudaGetSymbolAddress((void**)&m_hi, g_m_hi);
    cudaGetSymbolAddress((void**)&m_lo, g_m_lo);
    cudaGetSymbolAddress((void**)&p_hi, g_p_hi);
    cudaGetSymbolAddress((void**)&s, g_s);
    cudaGetSymbolAddress((void**)&pv, g_p_vec);
    cudaGetSymbolAddress((void**)&rv, g_r);

    static bool init_done = false;
    static cudaStream_t s1;
    static cudaEvent_t ev_fork, ev_ix, ev_io, ev_r;
    const int smem3 = 3 * 4 * TILE_B;   // 96 KB
    const int smem1 = 3 * 2 * TILE_B;   // 48 KB
    if (!init_done) {
        cudaFuncSetAttribute(gemm_split<3>,
                             cudaFuncAttributeMaxDynamicSharedMemorySize, smem3);
        cudaFuncSetAttribute(gemm_split<1>,
                             cudaFuncAttributeMaxDynamicSharedMemorySize, smem1);
        cudaStreamCreateWithFlags(&s1, cudaStreamNonBlocking);
        cudaEventCreateWithFlags(&ev_fork, cudaEventDisableTiming);
        cudaEventCreateWithFlags(&ev_ix,   cudaEventDisableTiming);
        cudaEventCreateWithFlags(&ev_io,   cudaEventDisableTiming);
        cudaEventCreateWithFlags(&ev_r,    cudaEventDisableTiming);
        init_done = true;
    }

    // ---- fork side stream ----
    cudaEventRecord(ev_fork, 0);
    cudaStreamWaitEvent(s1, ev_fork, 0);

    split_f32<<<(unsigned)(MELEMS / 4 / 256), 256, 0, s1>>>(ix, ix_hi, ix_lo, MELEMS);
    cudaEventRecord(ev_ix, s1);
    prep_io<<<dim3(LSEQ / 32, DIM / 32, BATCH), dim3(32, 8), 0, s1>>>(
        io, io_hi, io_lo, ioT_hi);
    cudaEventRecord(ev_io, s1);
    compute_p<<<DIM / 128, 128, 0, s1>>>(W, bb, pv);
    compute_r<<<(BATCH * LSEQ) / 8, 256, 0, s1>>>(io, pv, rv);
    cudaEventRecord(ev_r, s1);

    // ---- stream 0: GEMM chain ----
    transpose_split<<<dim3(DIM / 32, DIM / 32, 1), dim3(32, 8)>>>(
        W, wt_hi, wt_lo, DIM, DIM);

    // M = W^T W, split-K x4
    {
        dim3 g(DIM / 128, DIM / 128, 4);
        gemm_split<3><<<g, 256, smem3>>>(wt_hi, wt_lo, wt_hi, wt_lo,
                                         s, nullptr, nullptr,
                                         DIM / 4, DIM, DIM, DIM,
                                         DIM / 4, DIM / 4,
                                         (long long)DIM * DIM);
        combine_m<<<(DIM * DIM) / 4 / 256, 256>>>(s, m_hi, m_lo);
    }

    // t = ix @ M
    cudaStreamWaitEvent(0, ev_ix, 0);
    {
        dim3 g(DIM / 128, (BATCH * LSEQ) / 128, 1);
        gemm_split<3><<<g, 256, smem3>>>(ix_hi, ix_lo, m_hi, m_lo,
                                         nullptr, t_hi, t_lo,
                                         DIM, DIM, DIM, DIM, 0, 0, 0);
    }

    // scores
    cudaStreamWaitEvent(0, ev_io, 0);
    {
        dim3 g(LSEQ / 128, LSEQ / 128, BATCH);
        gemm_split<3><<<g, 256, smem3>>>(t_hi, t_lo, io_hi, io_lo,
                                         s, nullptr, nullptr,
                                         DIM, LSEQ, DIM, DIM,
                                         (long long)LSEQ * DIM,
                                         (long long)LSEQ * DIM,
                                         (long long)LSEQ * LSEQ);
    }

    // softmax(S + r) -> P fp16
    cudaStreamWaitEvent(0, ev_r, 0);
    softmax_h<<<BATCH * LSEQ, 256>>>(s, rv, p_hi, LSEQ);

    // out = P @ ioT^T (1-pass)
    {
        dim3 g(DIM / 128, LSEQ / 128, BATCH);
        gemm_split<1><<<g, 256, smem1>>>(p_hi, nullptr, ioT_hi, nullptr,
                                         out, nullptr, nullptr,
                                         LSEQ, DIM, LSEQ, LSEQ,
                                         (long long)LSEQ * LSEQ,
                                         (long long)DIM * LSEQ,
                                         (long long)LSEQ * DIM);
    }
}

// round 14
// speedup vs baseline: 1.0559x; 1.0559x over previous
#include <cuda_runtime.h>
#include <cuda_fp16.h>
#include <cstdint>
#include <math.h>

// ============================================================================
// Aligner: out = softmax((ix@W^T+b) @ (io@W^T+b)^T) @ io
// B=8, L=2048, D=1024, fp32 in/out.
// Round 14: R12 base (proven 1419us) + per-batch pipelining:
//   scores[b] / out[b] alternate across two GEMM streams (wave overlap keeps
//   SMs full); softmax[b] runs on the prep stream as soon as scores[b] ends,
//   hidden under later score batches. Numerics identical to R12.
// ============================================================================

#define BATCH 8
#define LSEQ  2048
#define DIM   1024
#define MELEMS ((size_t)BATCH * LSEQ * DIM)
#define SELEMS ((size_t)BATCH * LSEQ * LSEQ)

// ---- scratch (__device__ globals per allocation rules) ----
__device__ __half g_ix_hi[MELEMS],  g_ix_lo[MELEMS];
__device__ __half g_io_hi[MELEMS],  g_io_lo[MELEMS];
__device__ __half g_ioT_hi[MELEMS];
__device__ __half g_t_hi[MELEMS],   g_t_lo[MELEMS];
__device__ __half g_wt_hi[DIM * DIM], g_wt_lo[DIM * DIM];
__device__ __half g_m_hi[DIM * DIM],  g_m_lo[DIM * DIM];
__device__ float  g_s[SELEMS];                 // scores; head reused as M partials
__device__ __half g_p_hi[SELEMS];
__device__ float  g_p_vec[DIM];
__device__ float  g_r[(size_t)BATCH * LSEQ];

// ============================================================================
// PTX helpers (portable only)
// ============================================================================
__device__ __forceinline__ uint32_t smem_u32(const void* p) {
    uint32_t a;
    asm("{ .reg .u64 t; cvta.to.shared.u64 t, %1; cvt.u32.u64 %0, t; }"
        : "=r"(a) : "l"(p));
    return a;
}

#define CP_COMMIT() asm volatile("cp.async.commit_group;" ::: "memory")
#define CP_WAIT(N)  asm volatile("cp.async.wait_group %0;" :: "n"(N) : "memory")

__device__ __forceinline__ void cp16(uint32_t dst, const void* src) {
    asm volatile("cp.async.cg.shared.global [%0], [%1], 16;" :: "r"(dst), "l"(src));
}

__device__ __forceinline__ void ldsm4(uint32_t* r, uint32_t addr) {
    asm volatile("ldmatrix.sync.aligned.m8n8.x4.shared.b16 {%0,%1,%2,%3}, [%4];"
                 : "=r"(r[0]), "=r"(r[1]), "=r"(r[2]), "=r"(r[3]) : "r"(addr));
}

__device__ __forceinline__ void mma16816(float* d, const uint32_t* a,
                                         const uint32_t* b) {
    asm volatile(
        "mma.sync.aligned.m16n8k16.row.col.f32.f16.f16.f32 "
        "{%0,%1,%2,%3}, {%4,%5,%6,%7}, {%8,%9}, {%0,%1,%2,%3};"
        : "+f"(d[0]), "+f"(d[1]), "+f"(d[2]), "+f"(d[3])
        : "r"(a[0]), "r"(a[1]), "r"(a[2]), "r"(a[3]), "r"(b[0]), "r"(b[1]));
}

// tile layout: [rows][64 bytes], 16B chunks swizzled: chunk ^ ((row>>1)&3)
__device__ __forceinline__ uint32_t tile_addr(uint32_t base, int row, int chunk) {
    return base + row * 64 + ((chunk ^ ((row >> 1) & 3)) << 4);
}

// ============================================================================
// Helper kernels
// ============================================================================
__device__ __forceinline__ void split1(float v, __half& h, __half& l) {
    h = __float2half(v);
    l = __float2half(v - __half2float(h));
}

__global__ void split_f32(const float* __restrict__ s,
                          __half* __restrict__ hi,
                          __half* __restrict__ lo, size_t n) {
    size_t i = ((size_t)blockIdx.x * blockDim.x + threadIdx.x) * 4;
    if (i >= n) return;
    float4 v = *(const float4*)(s + i);
    __half h0, h1, h2, h3, l0, l1, l2, l3;
    split1(v.x, h0, l0); split1(v.y, h1, l1);
    split1(v.z, h2, l2); split1(v.w, h3, l3);
    *(__half2*)(hi + i)     = __halves2half2(h0, h1);
    *(__half2*)(hi + i + 2) = __halves2half2(h2, h3);
    *(__half2*)(lo + i)     = __halves2half2(l0, l1);
    *(__half2*)(lo + i + 2) = __halves2half2(l2, l3);
}

// fused io prep: reads io once; writes io_hi/io_lo and ioT_hi.
__global__ void prep_io(const float* __restrict__ src,
                        __half* __restrict__ hi, __half* __restrict__ lo,
                        __half* __restrict__ hiT) {
    __shared__ float t[32][33];
    int b = blockIdx.z;
    int l0 = blockIdx.x * 32, d0 = blockIdx.y * 32;
    const float* s = src + (size_t)b * LSEQ * DIM;
    __half* hb = hi + (size_t)b * LSEQ * DIM;
    __half* lb = lo + (size_t)b * LSEQ * DIM;
    #pragma unroll
    for (int i = 0; i < 32; i += 8) {
        float v = s[(size_t)(l0 + threadIdx.y + i) * DIM + d0 + threadIdx.x];
        t[threadIdx.y + i][threadIdx.x] = v;
        __half h, l;
        split1(v, h, l);
        size_t o = (size_t)(l0 + threadIdx.y + i) * DIM + d0 + threadIdx.x;
        hb[o] = h;
        lb[o] = l;
    }
    __syncthreads();
    size_t ob = (size_t)b * DIM * LSEQ;
    #pragma unroll
    for (int i = 0; i < 32; i += 8) {
        float v = t[threadIdx.x][threadIdx.y + i];
        hiT[ob + (size_t)(d0 + threadIdx.y + i) * LSEQ + l0 + threadIdx.x] =
            __float2half(v);
    }
}

// W transpose + split
__global__ void transpose_split(const float* __restrict__ src,
                                __half* __restrict__ hiT,
                                __half* __restrict__ loT,
                                int rows, int cols) {
    __shared__ float t[32][33];
    int r0 = blockIdx.x * 32, c0 = blockIdx.y * 32;
    #pragma unroll
    for (int i = 0; i < 32; i += 8)
        t[threadIdx.y + i][threadIdx.x] =
            src[(size_t)(r0 + threadIdx.y + i) * cols + c0 + threadIdx.x];
    __syncthreads();
    #pragma unroll
    for (int i = 0; i < 32; i += 8) {
        float v = t[threadIdx.x][threadIdx.y + i];
        __half h, l;
        split1(v, h, l);
        size_t o = (size_t)(c0 + threadIdx.y + i) * rows + r0 + threadIdx.x;
        hiT[o] = h;
        if (loT) loT[o] = l;
    }
}

// combine 4 fp32 split-K partials of M -> fp16 hi/lo
__global__ void combine_m(const float* __restrict__ parts,
                          __half* __restrict__ hi, __half* __restrict__ lo) {
    size_t i = ((size_t)blockIdx.x * blockDim.x + threadIdx.x) * 4;
    const size_t stride = (size_t)DIM * DIM;
    float4 a = *(const float4*)(parts + i);
    float4 b = *(const float4*)(parts + stride + i);
    float4 c = *(const float4*)(parts + 2 * stride + i);
    float4 d = *(const float4*)(parts + 3 * stride + i);
    float s0 = a.x + b.x + c.x + d.x;
    float s1 = a.y + b.y + c.y + d.y;
    float s2 = a.z + b.z + c.z + d.z;
    float s3 = a.w + b.w + c.w + d.w;
    __half h0, h1, h2, h3, l0, l1, l2, l3;
    split1(s0, h0, l0); split1(s1, h1, l1);
    split1(s2, h2, l2); split1(s3, h3, l3);
    *(__half2*)(hi + i)     = __halves2half2(h0, h1);
    *(__half2*)(hi + i + 2) = __halves2half2(h2, h3);
    *(__half2*)(lo + i)     = __halves2half2(l0, l1);
    *(__half2*)(lo + i + 2) = __halves2half2(l2, l3);
}

// p[i] = sum_k b[k] * W[k,i]
__global__ void compute_p(const float* __restrict__ W,
                          const float* __restrict__ b,
                          float* __restrict__ p) {
    int i = blockIdx.x * 128 + threadIdx.x;
    float acc = 0.f;
    for (int k = 0; k < DIM; ++k)
        acc += b[k] * W[(size_t)k * DIM + i];
    p[i] = acc;
}

// r[row] = io[row,:]·p
__global__ void compute_r(const float* __restrict__ io,
                          const float* __restrict__ p,
                          float* __restrict__ r) {
    int row  = blockIdx.x * 8 + (threadIdx.x >> 5);
    int lane = threadIdx.x & 31;
    const float* src = io + (size_t)row * DIM;
    float acc = 0.f;
    for (int d = lane * 4; d < DIM; d += 128) {
        float4 v  = *(const float4*)(src + d);
        float4 pv = *(const float4*)(p + d);
        acc += v.x * pv.x + v.y * pv.y + v.z * pv.z + v.w * pv.w;
    }
    #pragma unroll
    for (int o = 16; o; o >>= 1)
        acc += __shfl_xor_sync(0xFFFFFFFFu, acc, o);
    if (lane == 0) r[row] = acc;
}

// row softmax of (S[row,:] + r[:]); per-batch launch (grid = LSEQ rows).
__global__ void softmax_h(float* __restrict__ S,
                          const float* __restrict__ r,
                          __half* __restrict__ phi, int cols) {
    float* row = S + (size_t)blockIdx.x * cols;
    __half* hr = phi + (size_t)blockIdx.x * cols;
    const int tid = threadIdx.x;

    float lmax = -3.0e38f;
    for (int i = tid * 4; i < cols; i += 1024) {
        float4 v = *(const float4*)(row + i);
        float4 a = *(const float4*)(r + i);
        v.x += a.x; v.y += a.y; v.z += a.z; v.w += a.w;
        lmax = fmaxf(lmax, fmaxf(fmaxf(v.x, v.y), fmaxf(v.z, v.w)));
    }
    #pragma unroll
    for (int o = 16; o; o >>= 1)
        lmax = fmaxf(lmax, __shfl_xor_sync(0xFFFFFFFFu, lmax, o));
    __shared__ float sm[8], ss[8];
    if ((tid & 31) == 0) sm[tid >> 5] = lmax;
    __syncthreads();
    float rmax = fmaxf(fmaxf(fmaxf(sm[0], sm[1]), fmaxf(sm[2], sm[3])),
                       fmaxf(fmaxf(sm[4], sm[5]), fmaxf(sm[6], sm[7])));

    float lsum = 0.f;
    for (int i = tid * 4; i < cols; i += 1024) {
        float4 v = *(const float4*)(row + i);
        float4 a = *(const float4*)(r + i);
        v.x = expf(v.x + a.x - rmax); v.y = expf(v.y + a.y - rmax);
        v.z = expf(v.z + a.z - rmax); v.w = expf(v.w + a.w - rmax);
        *(float4*)(row + i) = v;
        lsum += v.x + v.y + v.z + v.w;
    }
    #pragma unroll
    for (int o = 16; o; o >>= 1)
        lsum += __shfl_xor_sync(0xFFFFFFFFu, lsum, o);
    if ((tid & 31) == 0) ss[tid >> 5] = lsum;
    __syncthreads();
    float inv = 1.f / (ss[0]+ss[1]+ss[2]+ss[3]+ss[4]+ss[5]+ss[6]+ss[7]);

    for (int i = tid * 4; i < cols; i += 1024) {
        float4 v = *(const float4*)(row + i);
        __half h0 = __float2half(v.x * inv);
        __half h1 = __float2half(v.y * inv);
        __half h2 = __float2half(v.z * inv);
        __half h3 = __float2half(v.w * inv);
        *(__half2*)(hr + i)     = __halves2half2(h0, h1);
        *(__half2*)(hr + i + 2) = __halves2half2(h2, h3);
    }
}

// ============================================================================
// Split-precision HMMA GEMM (R8/R12 proven config), CTA 128x128, warp 64x32,
// K-chunk 32, 3 smem stages, 2 CTAs/SM. lda/ldb in elements.
// NPASS=3: C = Ah*Bh + Ah*Bl + Al*Bh.   NPASS=1: C = Ah*Bh.
// ============================================================================
#define BKC 32
#define TILE_B 8192

template<int NPASS>
__global__ __launch_bounds__(256, 2)
void gemm_split(const __half* __restrict__ Ahi, const __half* __restrict__ Alo,
                const __half* __restrict__ Bhi, const __half* __restrict__ Blo,
                float* __restrict__ Cf,
                __half* __restrict__ Chi, __half* __restrict__ Clo,
                int K, int N, int lda, int ldb,
                long long sA, long long sB, long long sC)
{
    constexpr int NT = (NPASS == 3) ? 4 : 2;
    constexpr int STAGE_B = NT * TILE_B;
    constexpr int NSTAGE = 3;

    extern __shared__ __align__(128) char smem[];
    const uint32_t sb = smem_u32(smem);

    const int tid  = threadIdx.x;
    const int wid  = tid >> 5;
    const int lane = tid & 31;
    const int wm   = wid >> 2;
    const int wn   = wid & 3;

    const long long bz = blockIdx.z;
    const long long m0 = (long long)blockIdx.y * 128;
    const long long n0 = (long long)blockIdx.x * 128;

    const __half* srcs[4];
    int lds[4];
    srcs[0] = Ahi + bz * sA + m0 * lda; lds[0] = lda;
    if (NPASS == 3) {
        srcs[1] = Alo + bz * sA + m0 * lda; lds[1] = lda;
        srcs[2] = Bhi + bz * sB + n0 * ldb; lds[2] = ldb;
        srcs[3] = Blo + bz * sB + n0 * ldb; lds[3] = ldb;
    } else {
        srcs[1] = Bhi + bz * sB + n0 * ldb; lds[1] = ldb;
        srcs[2] = nullptr; lds[2] = 0;
        srcs[3] = nullptr; lds[3] = 0;
    }

    auto load_chunk = [&](int stage, int k0) {
        const uint32_t base = sb + stage * STAGE_B;
        #pragma unroll
        for (int t = 0; t < NT; ++t) {
            #pragma unroll
            for (int j = 0; j < 2; ++j) {
                int idx = tid * 2 + j;
                int row = idx >> 2;
                int ch  = idx & 3;
                cp16(tile_addr(base + t * TILE_B, row, ch),
                     srcs[t] + (long long)row * lds[t] + k0 + ch * 8);
            }
        }
        CP_COMMIT();
    };

    float acc[4][4][4];
    #pragma unroll
    for (int i = 0; i < 4; ++i)
        #pragma unroll
        for (int j = 0; j < 4; ++j)
            #pragma unroll
            for (int e = 0; e < 4; ++e) acc[i][j][e] = 0.f;

    const int NC = K >> 5;
    load_chunk(0, 0);
    load_chunk(1, BKC);

    const int lrow = lane & 15;
    const int lch  = lane >> 4;

    for (int c = 0; c < NC; ++c) {
        if (c + 1 < NC) CP_WAIT(1); else CP_WAIT(0);
        __syncthreads();
        if (c + 2 < NC) load_chunk((c + 2) % NSTAGE, (c + 2) * BKC);

        const uint32_t st  = sb + (c % NSTAGE) * STAGE_B;
        const uint32_t sAh = st;
        const uint32_t sAl = st + TILE_B;
        const uint32_t sBh = st + ((NPASS == 3) ? 2 : 1) * TILE_B;
        const uint32_t sBl = st + 3 * TILE_B;

        #pragma unroll
        for (int ks = 0; ks < 2; ++ks) {
            const int chunk = ks * 2 + lch;
            uint32_t ahi[4][4], alo[4][4];
            uint32_t bhi[4][2], blo[4][2];

            #pragma unroll
            for (int mi = 0; mi < 4; ++mi) {
                const int row = wm * 64 + mi * 16 + lrow;
                ldsm4(ahi[mi], tile_addr(sAh, row, chunk));
                if (NPASS == 3)
                    ldsm4(alo[mi], tile_addr(sAl, row, chunk));
            }
            #pragma unroll
            for (int bi = 0; bi < 2; ++bi) {
                const int row = wn * 32 + bi * 16 + lrow;
                uint32_t t4[4];
                ldsm4(t4, tile_addr(sBh, row, chunk));
                bhi[bi*2][0]   = t4[0]; bhi[bi*2][1]   = t4[2];
                bhi[bi*2+1][0] = t4[1]; bhi[bi*2+1][1] = t4[3];
                if (NPASS == 3) {
                    ldsm4(t4, tile_addr(sBl, row, chunk));
                    blo[bi*2][0]   = t4[0]; blo[bi*2][1]   = t4[2];
                    blo[bi*2+1][0] = t4[1]; blo[bi*2+1][1] = t4[3];
                }
            }

            #pragma unroll
            for (int mi = 0; mi < 4; ++mi)
                #pragma unroll
                for (int ni = 0; ni < 4; ++ni) {
                    mma16816(acc[mi][ni], ahi[mi], bhi[ni]);
                    if (NPASS == 3) {
                        mma16816(acc[mi][ni], ahi[mi], blo[ni]);
                        mma16816(acc[mi][ni], alo[mi], bhi[ni]);
                    }
                }
        }
        __syncthreads();
    }

    // ---- epilogue ----
    const int r1 = lane >> 2;
    const int c0 = (lane & 3) * 2;
    #pragma unroll
    for (int mi = 0; mi < 4; ++mi) {
        #pragma unroll
        for (int ni = 0; ni < 4; ++ni) {
            const long long gm = m0 + wm * 64 + mi * 16 + r1;
            const long long gn = n0 + wn * 32 + ni * 8 + c0;
            float v0 = acc[mi][ni][0], v1 = acc[mi][ni][1];
            float v2 = acc[mi][ni][2], v3 = acc[mi][ni][3];
            if (Cf) {
                float* d0 = Cf + bz * sC + gm * N + gn;
                float* d1 = Cf + bz * sC + (gm + 8) * N + gn;
                d0[0] = v0; d0[1] = v1;
                d1[0] = v2; d1[1] = v3;
            } else {
                __half h0, h1, h2, h3, l0, l1, l2, l3;
                split1(v0, h0, l0); split1(v1, h1, l1);
                split1(v2, h2, l2); split1(v3, h3, l3);
                *(__half2*)(Chi + bz * sC + gm * N + gn)       = __halves2half2(h0, h1);
                *(__half2*)(Clo + bz * sC + gm * N + gn)       = __halves2half2(l0, l1);
                *(__half2*)(Chi + bz * sC + (gm + 8) * N + gn) = __halves2half2(h2, h3);
                *(__half2*)(Clo + bz * sC + (gm + 8) * N + gn) = __halves2half2(l2, l3);
            }
        }
    }
}

// ============================================================================
extern "C" void kernel_launch(void* const* d_in, const int* in_sizes, int n_in,
                              void* d_out, int out_size)
{
    const float* ix = (const float*)d_in[0];
    const float* io = (const float*)d_in[1];
    const float* W  = (const float*)d_in[2];
    const float* bb = (const float*)d_in[3];
    float* out = (float*)d_out;

    __half *ix_hi, *ix_lo, *io_hi, *io_lo, *ioT_hi;
    __half *t_hi, *t_lo, *wt_hi, *wt_lo, *m_hi, *m_lo, *p_hi;
    float *s, *pv, *rv;
    cudaGetSymbolAddress((void**)&ix_hi, g_ix_hi);
    cudaGetSymbolAddress((void**)&ix_lo, g_ix_lo);
    cudaGetSymbolAddress((void**)&io_hi, g_io_hi);
    cudaGetSymbolAddress((void**)&io_lo, g_io_lo);
    cudaGetSymbolAddress((void**)&ioT_hi, g_ioT_hi);
    cudaGetSymbolAddress((void**)&t_hi, g_t_hi);
    cudaGetSymbolAddress((void**)&t_lo, g_t_lo);
    cudaGetSymbolAddress((void**)&wt_hi, g_wt_hi);
    cudaGetSymbolAddress((void**)&wt_lo, g_wt_lo);
    cudaGetSymbolAddress((void**)&m_hi, g_m_hi);
    cudaGetSymbolAddress((void**)&m_lo, g_m_lo);
    cudaGetSymbolAddress((void**)&p_hi, g_p_hi);
    cudaGetSymbolAddress((void**)&s, g_s);
    cudaGetSymbolAddress((void**)&pv, g_p_vec);
    cudaGetSymbolAddress((void**)&rv, g_r);

    static bool init_done = false;
    static cudaStream_t s1, s2;
    static cudaEvent_t ev_fork, ev_ix, ev_io, ev_r, ev_t;
    static cudaEvent_t ev_s[BATCH], ev_sm[BATCH];
    const int smem3 = 3 * 4 * TILE_B;   // 96 KB
    const int smem1 = 3 * 2 * TILE_B;   // 48 KB
    if (!init_done) {
        cudaFuncSetAttribute(gemm_split<3>,
                             cudaFuncAttributeMaxDynamicSharedMemorySize, smem3);
        cudaFuncSetAttribute(gemm_split<1>,
                             cudaFuncAttributeMaxDynamicSharedMemorySize, smem1);
        cudaStreamCreateWithFlags(&s1, cudaStreamNonBlocking);
        cudaStreamCreateWithFlags(&s2, cudaStreamNonBlocking);
        cudaEventCreateWithFlags(&ev_fork, cudaEventDisableTiming);
        cudaEventCreateWithFlags(&ev_ix,   cudaEventDisableTiming);
        cudaEventCreateWithFlags(&ev_io,   cudaEventDisableTiming);
        cudaEventCreateWithFlags(&ev_r,    cudaEventDisableTiming);
        cudaEventCreateWithFlags(&ev_t,    cudaEventDisableTiming);
        for (int b = 0; b < BATCH; ++b) {
            cudaEventCreateWithFlags(&ev_s[b],  cudaEventDisableTiming);
            cudaEventCreateWithFlags(&ev_sm[b], cudaEventDisableTiming);
        }
        init_done = true;
    }

    // ---- fork side streams ----
    cudaEventRecord(ev_fork, 0);
    cudaStreamWaitEvent(s1, ev_fork, 0);
    cudaStreamWaitEvent(s2, ev_fork, 0);

    // s1: prep kernels (overlap with M/t GEMMs on stream 0)
    split_f32<<<(unsigned)(MELEMS / 4 / 256), 256, 0, s1>>>(ix, ix_hi, ix_lo, MELEMS);
    cudaEventRecord(ev_ix, s1);
    prep_io<<<dim3(LSEQ / 32, DIM / 32, BATCH), dim3(32, 8), 0, s1>>>(
        io, io_hi, io_lo, ioT_hi);
    cudaEventRecord(ev_io, s1);
    compute_p<<<DIM / 128, 128, 0, s1>>>(W, bb, pv);
    compute_r<<<(BATCH * LSEQ) / 8, 256, 0, s1>>>(io, pv, rv);
    cudaEventRecord(ev_r, s1);

    // ---- stream 0: head of GEMM chain ----
    transpose_split<<<dim3(DIM / 32, DIM / 32, 1), dim3(32, 8)>>>(
        W, wt_hi, wt_lo, DIM, DIM);

    // M = W^T W, split-K x4 (fp32 partials in head of g_s), then combine
    {
        dim3 g(DIM / 128, DIM / 128, 4);
        gemm_split<3><<<g, 256, smem3>>>(wt_hi, wt_lo, wt_hi, wt_lo,
                                         s, nullptr, nullptr,
                                         DIM / 4, DIM, DIM, DIM,
                                         DIM / 4, DIM / 4,
                                         (long long)DIM * DIM);
        combine_m<<<(DIM * DIM) / 4 / 256, 256>>>(s, m_hi, m_lo);
    }

    // t = ix @ M (symmetric), 3-pass -> fp16 split
    cudaStreamWaitEvent(0, ev_ix, 0);
    {
        dim3 g(DIM / 128, (BATCH * LSEQ) / 128, 1);
        gemm_split<3><<<g, 256, smem3>>>(ix_hi, ix_lo, m_hi, m_lo,
                                         nullptr, t_hi, t_lo,
                                         DIM, DIM, DIM, DIM, 0, 0, 0);
    }
    cudaEventRecord(ev_t, 0);

    // scores per batch, alternating stream 0 / s2 (waves overlap -> full SMs)
    cudaStreamWaitEvent(0,  ev_io, 0);
    cudaStreamWaitEvent(s2, ev_io, 0);
    cudaStreamWaitEvent(s2, ev_t, 0);
    for (int b = 0; b < BATCH; ++b) {
        cudaStream_t st = (b & 1) ? s2 : (cudaStream_t)0;
        dim3 g(LSEQ / 128, LSEQ / 128, 1);
        gemm_split<3><<<g, 256, smem3, st>>>(
            t_hi + (size_t)b * LSEQ * DIM, t_lo + (size_t)b * LSEQ * DIM,
            io_hi + (size_t)b * LSEQ * DIM, io_lo + (size_t)b * LSEQ * DIM,
            s + (size_t)b * LSEQ * LSEQ, nullptr, nullptr,
            DIM, LSEQ, DIM, DIM, 0, 0, 0);
        cudaEventRecord(ev_s[b], st);
    }

    // softmax per batch on s1 (hidden under later score batches)
    for (int b = 0; b < BATCH; ++b) {
        cudaStreamWaitEvent(s1, ev_s[b], 0);
        softmax_h<<<LSEQ, 256, 0, s1>>>(
            s + (size_t)b * LSEQ * LSEQ, rv + (size_t)b * LSEQ,
            p_hi + (size_t)b * LSEQ * LSEQ, LSEQ);
        cudaEventRecord(ev_sm[b], s1);
    }

    // out per batch, alternating stream 0 / s2
    for (int b = 0; b < BATCH; ++b) {
        cudaStream_t st = (b & 1) ? s2 : (cudaStream_t)0;
        cudaStreamWaitEvent(st, ev_sm[b], 0);
        dim3 g(DIM / 128, LSEQ / 128, 1);
        gemm_split<1><<<g, 256, smem1, st>>>(
            p_hi + (size_t)b * LSEQ * LSEQ, nullptr,
            ioT_hi + (size_t)b * DIM * LSEQ, nullptr,
            out + (size_t)b * LSEQ * DIM, nullptr, nullptr,
            LSEQ, DIM, LSEQ, LSEQ, 0, 0, 0);
    }

    // join s2 back into stream 0 (harness times stream 0)
    cudaEventRecord(ev_fork, s2);
    cudaStreamWaitEvent(0, ev_fork, 0);
}

// round 16
// speedup vs baseline: 1.0951x; 1.0371x over previous
#include <cuda_runtime.h>
#include <cuda_fp16.h>
#include <cstdint>
#include <math.h>

// ============================================================================
// Aligner: out = softmax((ix@W^T+b) @ (io@W^T+b)^T) @ io
// B=8, L=2048, D=1024, fp32 in/out.
// Round 16: R15 with the softmax loop bound FIXED (2 float4/thread for
// cols=2048, not 8 — R15 read 6KB past each row). Single-pass register
// softmax + M split-K x8 + R12 schedule. GEMM core unchanged.
// ============================================================================

#define BATCH 8
#define LSEQ  2048
#define DIM   1024
#define MELEMS ((size_t)BATCH * LSEQ * DIM)
#define SELEMS ((size_t)BATCH * LSEQ * LSEQ)

// ---- scratch (__device__ globals per allocation rules) ----
__device__ __half g_ix_hi[MELEMS],  g_ix_lo[MELEMS];
__device__ __half g_io_hi[MELEMS],  g_io_lo[MELEMS];
__device__ __half g_ioT_hi[MELEMS];
__device__ __half g_t_hi[MELEMS],   g_t_lo[MELEMS];
__device__ __half g_wt_hi[DIM * DIM], g_wt_lo[DIM * DIM];
__device__ __half g_m_hi[DIM * DIM],  g_m_lo[DIM * DIM];
__device__ float  g_s[SELEMS];                 // scores; head reused as M partials
__device__ __half g_p_hi[SELEMS];
__device__ float  g_p_vec[DIM];
__device__ float  g_r[(size_t)BATCH * LSEQ];

// ============================================================================
// PTX helpers (portable only)
// ============================================================================
__device__ __forceinline__ uint32_t smem_u32(const void* p) {
    uint32_t a;
    asm("{ .reg .u64 t; cvta.to.shared.u64 t, %1; cvt.u32.u64 %0, t; }"
        : "=r"(a) : "l"(p));
    return a;
}

#define CP_COMMIT() asm volatile("cp.async.commit_group;" ::: "memory")
#define CP_WAIT(N)  asm volatile("cp.async.wait_group %0;" :: "n"(N) : "memory")

__device__ __forceinline__ void cp16(uint32_t dst, const void* src) {
    asm volatile("cp.async.cg.shared.global [%0], [%1], 16;" :: "r"(dst), "l"(src));
}

__device__ __forceinline__ void ldsm4(uint32_t* r, uint32_t addr) {
    asm volatile("ldmatrix.sync.aligned.m8n8.x4.shared.b16 {%0,%1,%2,%3}, [%4];"
                 : "=r"(r[0]), "=r"(r[1]), "=r"(r[2]), "=r"(r[3]) : "r"(addr));
}

__device__ __forceinline__ void mma16816(float* d, const uint32_t* a,
                                         const uint32_t* b) {
    asm volatile(
        "mma.sync.aligned.m16n8k16.row.col.f32.f16.f16.f32 "
        "{%0,%1,%2,%3}, {%4,%5,%6,%7}, {%8,%9}, {%0,%1,%2,%3};"
        : "+f"(d[0]), "+f"(d[1]), "+f"(d[2]), "+f"(d[3])
        : "r"(a[0]), "r"(a[1]), "r"(a[2]), "r"(a[3]), "r"(b[0]), "r"(b[1]));
}

// tile layout: [rows][64 bytes], 16B chunks swizzled: chunk ^ ((row>>1)&3)
__device__ __forceinline__ uint32_t tile_addr(uint32_t base, int row, int chunk) {
    return base + row * 64 + ((chunk ^ ((row >> 1) & 3)) << 4);
}

// ============================================================================
// Helper kernels
// ============================================================================
__device__ __forceinline__ void split1(float v, __half& h, __half& l) {
    h = __float2half(v);
    l = __float2half(v - __half2float(h));
}

__global__ void split_f32(const float* __restrict__ s,
                          __half* __restrict__ hi,
                          __half* __restrict__ lo, size_t n) {
    size_t i = ((size_t)blockIdx.x * blockDim.x + threadIdx.x) * 4;
    if (i >= n) return;
    float4 v = *(const float4*)(s + i);
    __half h0, h1, h2, h3, l0, l1, l2, l3;
    split1(v.x, h0, l0); split1(v.y, h1, l1);
    split1(v.z, h2, l2); split1(v.w, h3, l3);
    *(__half2*)(hi + i)     = __halves2half2(h0, h1);
    *(__half2*)(hi + i + 2) = __halves2half2(h2, h3);
    *(__half2*)(lo + i)     = __halves2half2(l0, l1);
    *(__half2*)(lo + i + 2) = __halves2half2(l2, l3);
}

// fused io prep: reads io once; writes io_hi/io_lo and ioT_hi.
__global__ void prep_io(const float* __restrict__ src,
                        __half* __restrict__ hi, __half* __restrict__ lo,
                        __half* __restrict__ hiT) {
    __shared__ float t[32][33];
    int b = blockIdx.z;
    int l0 = blockIdx.x * 32, d0 = blockIdx.y * 32;
    const float* s = src + (size_t)b * LSEQ * DIM;
    __half* hb = hi + (size_t)b * LSEQ * DIM;
    __half* lb = lo + (size_t)b * LSEQ * DIM;
    #pragma unroll
    for (int i = 0; i < 32; i += 8) {
        float v = s[(size_t)(l0 + threadIdx.y + i) * DIM + d0 + threadIdx.x];
        t[threadIdx.y + i][threadIdx.x] = v;
        __half h, l;
        split1(v, h, l);
        size_t o = (size_t)(l0 + threadIdx.y + i) * DIM + d0 + threadIdx.x;
        hb[o] = h;
        lb[o] = l;
    }
    __syncthreads();
    size_t ob = (size_t)b * DIM * LSEQ;
    #pragma unroll
    for (int i = 0; i < 32; i += 8) {
        float v = t[threadIdx.x][threadIdx.y + i];
        hiT[ob + (size_t)(d0 + threadIdx.y + i) * LSEQ + l0 + threadIdx.x] =
            __float2half(v);
    }
}

// W transpose + split
__global__ void transpose_split(const float* __restrict__ src,
                                __half* __restrict__ hiT,
                                __half* __restrict__ loT,
                                int rows, int cols) {
    __shared__ float t[32][33];
    int r0 = blockIdx.x * 32, c0 = blockIdx.y * 32;
    #pragma unroll
    for (int i = 0; i < 32; i += 8)
        t[threadIdx.y + i][threadIdx.x] =
            src[(size_t)(r0 + threadIdx.y + i) * cols + c0 + threadIdx.x];
    __syncthreads();
    #pragma unroll
    for (int i = 0; i < 32; i += 8) {
        float v = t[threadIdx.x][threadIdx.y + i];
        __half h, l;
        split1(v, h, l);
        size_t o = (size_t)(c0 + threadIdx.y + i) * rows + r0 + threadIdx.x;
        hiT[o] = h;
        if (loT) loT[o] = l;
    }
}

// combine 8 fp32 split-K partials of M -> fp16 hi/lo
__global__ void combine_m(const float* __restrict__ parts,
                          __half* __restrict__ hi, __half* __restrict__ lo) {
    size_t i = ((size_t)blockIdx.x * blockDim.x + threadIdx.x) * 4;
    const size_t stride = (size_t)DIM * DIM;
    float s0 = 0.f, s1 = 0.f, s2 = 0.f, s3 = 0.f;
    #pragma unroll
    for (int k = 0; k < 8; ++k) {
        float4 v = *(const float4*)(parts + k * stride + i);
        s0 += v.x; s1 += v.y; s2 += v.z; s3 += v.w;
    }
    __half h0, h1, h2, h3, l0, l1, l2, l3;
    split1(s0, h0, l0); split1(s1, h1, l1);
    split1(s2, h2, l2); split1(s3, h3, l3);
    *(__half2*)(hi + i)     = __halves2half2(h0, h1);
    *(__half2*)(hi + i + 2) = __halves2half2(h2, h3);
    *(__half2*)(lo + i)     = __halves2half2(l0, l1);
    *(__half2*)(lo + i + 2) = __halves2half2(l2, l3);
}

// p[i] = sum_k b[k] * W[k,i]
__global__ void compute_p(const float* __restrict__ W,
                          const float* __restrict__ b,
                          float* __restrict__ p) {
    int i = blockIdx.x * 128 + threadIdx.x;
    float acc = 0.f;
    for (int k = 0; k < DIM; ++k)
        acc += b[k] * W[(size_t)k * DIM + i];
    p[i] = acc;
}

// r[row] = io[row,:]·p
__global__ void compute_r(const float* __restrict__ io,
                          const float* __restrict__ p,
                          float* __restrict__ r) {
    int row  = blockIdx.x * 8 + (threadIdx.x >> 5);
    int lane = threadIdx.x & 31;
    const float* src = io + (size_t)row * DIM;
    float acc = 0.f;
    for (int d = lane * 4; d < DIM; d += 128) {
        float4 v  = *(const float4*)(src + d);
        float4 pv = *(const float4*)(p + d);
        acc += v.x * pv.x + v.y * pv.y + v.z * pv.z + v.w * pv.w;
    }
    #pragma unroll
    for (int o = 16; o; o >>= 1)
        acc += __shfl_xor_sync(0xFFFFFFFFu, acc, o);
    if (lane == 0) r[row] = acc;
}

// Single-pass register-resident softmax of (S[row,:] + r[b,:]) -> P fp16.
// cols = 2048, 256 threads/row: each thread holds exactly 2 float4 (8 vals).
__global__ void softmax_h(const float* __restrict__ S,
                          const float* __restrict__ r,
                          __half* __restrict__ phi, int cols) {
    const float* row = S + (size_t)blockIdx.x * cols;
    const float* rr = r + (size_t)(blockIdx.x / LSEQ) * LSEQ;
    __half* hr = phi + (size_t)blockIdx.x * cols;
    const int tid = threadIdx.x;

    float4 v[2];
    float lmax = -3.0e38f;
    #pragma unroll
    for (int j = 0; j < 2; ++j) {
        int i = tid * 4 + j * 1024;
        v[j] = *(const float4*)(row + i);
        float4 a = *(const float4*)(rr + i);
        v[j].x += a.x; v[j].y += a.y; v[j].z += a.z; v[j].w += a.w;
        lmax = fmaxf(lmax, fmaxf(fmaxf(v[j].x, v[j].y), fmaxf(v[j].z, v[j].w)));
    }
    #pragma unroll
    for (int o = 16; o; o >>= 1)
        lmax = fmaxf(lmax, __shfl_xor_sync(0xFFFFFFFFu, lmax, o));
    __shared__ float sm[8], ss[8];
    if ((tid & 31) == 0) sm[tid >> 5] = lmax;
    __syncthreads();
    float rmax = fmaxf(fmaxf(fmaxf(sm[0], sm[1]), fmaxf(sm[2], sm[3])),
                       fmaxf(fmaxf(sm[4], sm[5]), fmaxf(sm[6], sm[7])));

    float lsum = 0.f;
    #pragma unroll
    for (int j = 0; j < 2; ++j) {
        v[j].x = expf(v[j].x - rmax); v[j].y = expf(v[j].y - rmax);
        v[j].z = expf(v[j].z - rmax); v[j].w = expf(v[j].w - rmax);
        lsum += v[j].x + v[j].y + v[j].z + v[j].w;
    }
    #pragma unroll
    for (int o = 16; o; o >>= 1)
        lsum += __shfl_xor_sync(0xFFFFFFFFu, lsum, o);
    if ((tid & 31) == 0) ss[tid >> 5] = lsum;
    __syncthreads();
    float inv = 1.f / (ss[0]+ss[1]+ss[2]+ss[3]+ss[4]+ss[5]+ss[6]+ss[7]);

    #pragma unroll
    for (int j = 0; j < 2; ++j) {
        int i = tid * 4 + j * 1024;
        __half h0 = __float2half(v[j].x * inv);
        __half h1 = __float2half(v[j].y * inv);
        __half h2 = __float2half(v[j].z * inv);
        __half h3 = __float2half(v[j].w * inv);
        *(__half2*)(hr + i)     = __halves2half2(h0, h1);
        *(__half2*)(hr + i + 2) = __halves2half2(h2, h3);
    }
}

// ============================================================================
// Split-precision HMMA GEMM (proven config), CTA 128x128, warp 64x32,
// K-chunk 32, 3 smem stages, 2 CTAs/SM. lda/ldb in elements.
// NPASS=3: C = Ah*Bh + Ah*Bl + Al*Bh.   NPASS=1: C = Ah*Bh.
// ============================================================================
#define BKC 32
#define TILE_B 8192

template<int NPASS>
__global__ __launch_bounds__(256, 2)
void gemm_split(const __half* __restrict__ Ahi, const __half* __restrict__ Alo,
                const __half* __restrict__ Bhi, const __half* __restrict__ Blo,
                float* __restrict__ Cf,
                __half* __restrict__ Chi, __half* __restrict__ Clo,
                int K, int N, int lda, int ldb,
                long long sA, long long sB, long long sC)
{
    constexpr int NT = (NPASS == 3) ? 4 : 2;
    constexpr int STAGE_B = NT * TILE_B;
    constexpr int NSTAGE = 3;

    extern __shared__ __align__(128) char smem[];
    const uint32_t sb = smem_u32(smem);

    const int tid  = threadIdx.x;
    const int wid  = tid >> 5;
    const int lane = tid & 31;
    const int wm   = wid >> 2;
    const int wn   = wid & 3;

    const long long bz = blockIdx.z;
    const long long m0 = (long long)blockIdx.y * 128;
    const long long n0 = (long long)blockIdx.x * 128;

    const __half* srcs[4];
    int lds[4];
    srcs[0] = Ahi + bz * sA + m0 * lda; lds[0] = lda;
    if (NPASS == 3) {
        srcs[1] = Alo + bz * sA + m0 * lda; lds[1] = lda;
        srcs[2] = Bhi + bz * sB + n0 * ldb; lds[2] = ldb;
        srcs[3] = Blo + bz * sB + n0 * ldb; lds[3] = ldb;
    } else {
        srcs[1] = Bhi + bz * sB + n0 * ldb; lds[1] = ldb;
        srcs[2] = nullptr; lds[2] = 0;
        srcs[3] = nullptr; lds[3] = 0;
    }

    auto load_chunk = [&](int stage, int k0) {
        const uint32_t base = sb + stage * STAGE_B;
        #pragma unroll
        for (int t = 0; t < NT; ++t) {
            #pragma unroll
            for (int j = 0; j < 2; ++j) {
                int idx = tid * 2 + j;
                int row = idx >> 2;
                int ch  = idx & 3;
                cp16(tile_addr(base + t * TILE_B, row, ch),
                     srcs[t] + (long long)row * lds[t] + k0 + ch * 8);
            }
        }
        CP_COMMIT();
    };

    float acc[4][4][4];
    #pragma unroll
    for (int i = 0; i < 4; ++i)
        #pragma unroll
        for (int j = 0; j < 4; ++j)
            #pragma unroll
            for (int e = 0; e < 4; ++e) acc[i][j][e] = 0.f;

    const int NC = K >> 5;
    load_chunk(0, 0);
    load_chunk(1, BKC);

    const int lrow = lane & 15;
    const int lch  = lane >> 4;

    for (int c = 0; c < NC; ++c) {
        if (c + 1 < NC) CP_WAIT(1); else CP_WAIT(0);
        __syncthreads();
        if (c + 2 < NC) load_chunk((c + 2) % NSTAGE, (c + 2) * BKC);

        const uint32_t st  = sb + (c % NSTAGE) * STAGE_B;
        const uint32_t sAh = st;
        const uint32_t sAl = st + TILE_B;
        const uint32_t sBh = st + ((NPASS == 3) ? 2 : 1) * TILE_B;
        const uint32_t sBl = st + 3 * TILE_B;

        #pragma unroll
        for (int ks = 0; ks < 2; ++ks) {
            const int chunk = ks * 2 + lch;
            uint32_t ahi[4][4], alo[4][4];
            uint32_t bhi[4][2], blo[4][2];

            #pragma unroll
            for (int mi = 0; mi < 4; ++mi) {
                const int row = wm * 64 + mi * 16 + lrow;
                ldsm4(ahi[mi], tile_addr(sAh, row, chunk));
                if (NPASS == 3)
                    ldsm4(alo[mi], tile_addr(sAl, row, chunk));
            }
            #pragma unroll
            for (int bi = 0; bi < 2; ++bi) {
                const int row = wn * 32 + bi * 16 + lrow;
                uint32_t t4[4];
                ldsm4(t4, tile_addr(sBh, row, chunk));
                bhi[bi*2][0]   = t4[0]; bhi[bi*2][1]   = t4[2];
                bhi[bi*2+1][0] = t4[1]; bhi[bi*2+1][1] = t4[3];
                if (NPASS == 3) {
                    ldsm4(t4, tile_addr(sBl, row, chunk));
                    blo[bi*2][0]   = t4[0]; blo[bi*2][1]   = t4[2];
                    blo[bi*2+1][0] = t4[1]; blo[bi*2+1][1] = t4[3];
                }
            }

            #pragma unroll
            for (int mi = 0; mi < 4; ++mi)
                #pragma unroll
                for (int ni = 0; ni < 4; ++ni) {
                    mma16816(acc[mi][ni], ahi[mi], bhi[ni]);
                    if (NPASS == 3) {
                        mma16816(acc[mi][ni], ahi[mi], blo[ni]);
                        mma16816(acc[mi][ni], alo[mi], bhi[ni]);
                    }
                }
        }
        __syncthreads();
    }

    // ---- epilogue ----
    const int r1 = lane >> 2;
    const int c0 = (lane & 3) * 2;
    #pragma unroll
    for (int mi = 0; mi < 4; ++mi) {
        #pragma unroll
        for (int ni = 0; ni < 4; ++ni) {
            const long long gm = m0 + wm * 64 + mi * 16 + r1;
            const long long gn = n0 + wn * 32 + ni * 8 + c0;
            float v0 = acc[mi][ni][0], v1 = acc[mi][ni][1];
            float v2 = acc[mi][ni][2], v3 = acc[mi][ni][3];
            if (Cf) {
                float* d0 = Cf + bz * sC + gm * N + gn;
                float* d1 = Cf + bz * sC + (gm + 8) * N + gn;
                d0[0] = v0; d0[1] = v1;
                d1[0] = v2; d1[1] = v3;
            } else {
                __half h0, h1, h2, h3, l0, l1, l2, l3;
                split1(v0, h0, l0); split1(v1, h1, l1);
                split1(v2, h2, l2); split1(v3, h3, l3);
                *(__half2*)(Chi + bz * sC + gm * N + gn)       = __halves2half2(h0, h1);
                *(__half2*)(Clo + bz * sC + gm * N + gn)       = __halves2half2(l0, l1);
                *(__half2*)(Chi + bz * sC + (gm + 8) * N + gn) = __halves2half2(h2, h3);
                *(__half2*)(Clo + bz * sC + (gm + 8) * N + gn) = __halves2half2(l2, l3);
            }
        }
    }
}

// ============================================================================
extern "C" void kernel_launch(void* const* d_in, const int* in_sizes, int n_in,
                              void* d_out, int out_size)
{
    const float* ix = (const float*)d_in[0];
    const float* io = (const float*)d_in[1];
    const float* W  = (const float*)d_in[2];
    const float* bb = (const float*)d_in[3];
    float* out = (float*)d_out;

    __half *ix_hi, *ix_lo, *io_hi, *io_lo, *ioT_hi;
    __half *t_hi, *t_lo, *wt_hi, *wt_lo, *m_hi, *m_lo, *p_hi;
    float *s, *pv, *rv;
    cudaGetSymbolAddress((void**)&ix_hi, g_ix_hi);
    cudaGetSymbolAddress((void**)&ix_lo, g_ix_lo);
    cudaGetSymbolAddress((void**)&io_hi, g_io_hi);
    cudaGetSymbolAddress((void**)&io_lo, g_io_lo);
    cudaGetSymbolAddress((void**)&ioT_hi, g_ioT_hi);
    cudaGetSymbolAddress((void**)&t_hi, g_t_hi);
    cudaGetSymbolAddress((void**)&t_lo, g_t_lo);
    cudaGetSymbolAddress((void**)&wt_hi, g_wt_hi);
    cudaGetSymbolAddress((void**)&wt_lo, g_wt_lo);
    cudaGetSymbolAddress((void**)&m_hi, g_m_hi);
    cudaGetSymbolAddress((void**)&m_lo, g_m_lo);
    cudaGetSymbolAddress((void**)&p_hi, g_p_hi);
    cudaGetSymbolAddress((void**)&s, g_s);
    cudaGetSymbolAddress((void**)&pv, g_p_vec);
    cudaGetSymbolAddress((void**)&rv, g_r);

    static bool init_done = false;
    static cudaStream_t s1;
    static cudaEvent_t ev_fork, ev_ix, ev_io, ev_r;
    const int smem3 = 3 * 4 * TILE_B;   // 96 KB
    const int smem1 = 3 * 2 * TILE_B;   // 48 KB
    if (!init_done) {
        cudaFuncSetAttribute(gemm_split<3>,
                             cudaFuncAttributeMaxDynamicSharedMemorySize, smem3);
        cudaFuncSetAttribute(gemm_split<1>,
                             cudaFuncAttributeMaxDynamicSharedMemorySize, smem1);
        cudaStreamCreateWithFlags(&s1, cudaStreamNonBlocking);
        cudaEventCreateWithFlags(&ev_fork, cudaEventDisableTiming);
        cudaEventCreateWithFlags(&ev_ix,   cudaEventDisableTiming);
        cudaEventCreateWithFlags(&ev_io,   cudaEventDisableTiming);
        cudaEventCreateWithFlags(&ev_r,    cudaEventDisableTiming);
        init_done = true;
    }

    // ---- fork side stream ----
    cudaEventRecord(ev_fork, 0);
    cudaStreamWaitEvent(s1, ev_fork, 0);

    // s1: prep kernels (overlap with M/t GEMMs on stream 0)
    split_f32<<<(unsigned)(MELEMS / 4 / 256), 256, 0, s1>>>(ix, ix_hi, ix_lo, MELEMS);
    cudaEventRecord(ev_ix, s1);
    prep_io<<<dim3(LSEQ / 32, DIM / 32, BATCH), dim3(32, 8), 0, s1>>>(
        io, io_hi, io_lo, ioT_hi);
    cudaEventRecord(ev_io, s1);
    compute_p<<<DIM / 128, 128, 0, s1>>>(W, bb, pv);
    compute_r<<<(BATCH * LSEQ) / 8, 256, 0, s1>>>(io, pv, rv);
    cudaEventRecord(ev_r, s1);

    // ---- stream 0: GEMM chain ----
    transpose_split<<<dim3(DIM / 32, DIM / 32, 1), dim3(32, 8)>>>(
        W, wt_hi, wt_lo, DIM, DIM);

    // M = W^T W, split-K x8 (fp32 partials in head of g_s), then combine
    {
        dim3 g(DIM / 128, DIM / 128, 8);
        gemm_split<3><<<g, 256, smem3>>>(wt_hi, wt_lo, wt_hi, wt_lo,
                                         s, nullptr, nullptr,
                                         DIM / 8, DIM, DIM, DIM,
                                         DIM / 8, DIM / 8,
                                         (long long)DIM * DIM);
        combine_m<<<(DIM * DIM) / 4 / 256, 256>>>(s, m_hi, m_lo);
    }

    // t = ix @ M (symmetric), 3-pass -> fp16 split
    cudaStreamWaitEvent(0, ev_ix, 0);
    {
        dim3 g(DIM / 128, (BATCH * LSEQ) / 128, 1);
        gemm_split<3><<<g, 256, smem3>>>(ix_hi, ix_lo, m_hi, m_lo,
                                         nullptr, t_hi, t_lo,
                                         DIM, DIM, DIM, DIM, 0, 0, 0);
    }

    // scores: S[b] = t[b] @ io[b]^T, 3-pass -> fp32
    cudaStreamWaitEvent(0, ev_io, 0);
    {
        dim3 g(LSEQ / 128, LSEQ / 128, BATCH);
        gemm_split<3><<<g, 256, smem3>>>(t_hi, t_lo, io_hi, io_lo,
                                         s, nullptr, nullptr,
                                         DIM, LSEQ, DIM, DIM,
                                         (long long)LSEQ * DIM,
                                         (long long)LSEQ * DIM,
                                         (long long)LSEQ * LSEQ);
    }

    // softmax(S + r) -> P fp16 (single-pass, register-resident)
    cudaStreamWaitEvent(0, ev_r, 0);
    softmax_h<<<BATCH * LSEQ, 256>>>(s, rv, p_hi, LSEQ);

    // out = P @ ioT^T (1-pass)
    {
        dim3 g(DIM / 128, LSEQ / 128, BATCH);
        gemm_split<1><<<g, 256, smem1>>>(p_hi, nullptr, ioT_hi, nullptr,
                                         out, nullptr, nullptr,
                                         LSEQ, DIM, LSEQ, LSEQ,
                                         (long long)LSEQ * LSEQ,
                                         (long long)DIM * LSEQ,
                                         (long long)LSEQ * DIM);
    }
}

// round 17
// speedup vs baseline: 1.0951x; 1.0000x over previous
#include <cuda_runtime.h>
#include <cuda_fp16.h>
#include <cstdint>
#include <math.h>

// ============================================================================
// Aligner: out = softmax((ix@W^T+b) @ (io@W^T+b)^T) @ io
// B=8, L=2048, D=1024, fp32 in/out.
// Round 17: R16 numerics + half-batch dual-stream pipeline:
//   scores(b0-3)@stream0 || scores(b4-7)@s2; softmax halves on s1 hidden in
//   the gaps; out halves follow per-stream. Only the last out tail is exposed.
// ============================================================================

#define BATCH 8
#define LSEQ  2048
#define DIM   1024
#define MELEMS ((size_t)BATCH * LSEQ * DIM)
#define SELEMS ((size_t)BATCH * LSEQ * LSEQ)
#define HB     (BATCH / 2)

// ---- scratch (__device__ globals per allocation rules) ----
__device__ __half g_ix_hi[MELEMS],  g_ix_lo[MELEMS];
__device__ __half g_io_hi[MELEMS],  g_io_lo[MELEMS];
__device__ __half g_ioT_hi[MELEMS];
__device__ __half g_t_hi[MELEMS],   g_t_lo[MELEMS];
__device__ __half g_wt_hi[DIM * DIM], g_wt_lo[DIM * DIM];
__device__ __half g_m_hi[DIM * DIM],  g_m_lo[DIM * DIM];
__device__ float  g_s[SELEMS];                 // scores; head reused as M partials
__device__ __half g_p_hi[SELEMS];
__device__ float  g_p_vec[DIM];
__device__ float  g_r[(size_t)BATCH * LSEQ];

// ============================================================================
// PTX helpers (portable only)
// ============================================================================
__device__ __forceinline__ uint32_t smem_u32(const void* p) {
    uint32_t a;
    asm("{ .reg .u64 t; cvta.to.shared.u64 t, %1; cvt.u32.u64 %0, t; }"
        : "=r"(a) : "l"(p));
    return a;
}

#define CP_COMMIT() asm volatile("cp.async.commit_group;" ::: "memory")
#define CP_WAIT(N)  asm volatile("cp.async.wait_group %0;" :: "n"(N) : "memory")

__device__ __forceinline__ void cp16(uint32_t dst, const void* src) {
    asm volatile("cp.async.cg.shared.global [%0], [%1], 16;" :: "r"(dst), "l"(src));
}

__device__ __forceinline__ void ldsm4(uint32_t* r, uint32_t addr) {
    asm volatile("ldmatrix.sync.aligned.m8n8.x4.shared.b16 {%0,%1,%2,%3}, [%4];"
                 : "=r"(r[0]), "=r"(r[1]), "=r"(r[2]), "=r"(r[3]) : "r"(addr));
}

__device__ __forceinline__ void mma16816(float* d, const uint32_t* a,
                                         const uint32_t* b) {
    asm volatile(
        "mma.sync.aligned.m16n8k16.row.col.f32.f16.f16.f32 "
        "{%0,%1,%2,%3}, {%4,%5,%6,%7}, {%8,%9}, {%0,%1,%2,%3};"
        : "+f"(d[0]), "+f"(d[1]), "+f"(d[2]), "+f"(d[3])
        : "r"(a[0]), "r"(a[1]), "r"(a[2]), "r"(a[3]), "r"(b[0]), "r"(b[1]));
}

// tile layout: [rows][64 bytes], 16B chunks swizzled: chunk ^ ((row>>1)&3)
__device__ __forceinline__ uint32_t tile_addr(uint32_t base, int row, int chunk) {
    return base + row * 64 + ((chunk ^ ((row >> 1) & 3)) << 4);
}

// ============================================================================
// Helper kernels
// ============================================================================
__device__ __forceinline__ void split1(float v, __half& h, __half& l) {
    h = __float2half(v);
    l = __float2half(v - __half2float(h));
}

__global__ void split_f32(const float* __restrict__ s,
                          __half* __restrict__ hi,
                          __half* __restrict__ lo, size_t n) {
    size_t i = ((size_t)blockIdx.x * blockDim.x + threadIdx.x) * 4;
    if (i >= n) return;
    float4 v = *(const float4*)(s + i);
    __half h0, h1, h2, h3, l0, l1, l2, l3;
    split1(v.x, h0, l0); split1(v.y, h1, l1);
    split1(v.z, h2, l2); split1(v.w, h3, l3);
    *(__half2*)(hi + i)     = __halves2half2(h0, h1);
    *(__half2*)(hi + i + 2) = __halves2half2(h2, h3);
    *(__half2*)(lo + i)     = __halves2half2(l0, l1);
    *(__half2*)(lo + i + 2) = __halves2half2(l2, l3);
}

// fused io prep: reads io once; writes io_hi/io_lo and ioT_hi.
__global__ void prep_io(const float* __restrict__ src,
                        __half* __restrict__ hi, __half* __restrict__ lo,
                        __half* __restrict__ hiT) {
    __shared__ float t[32][33];
    int b = blockIdx.z;
    int l0 = blockIdx.x * 32, d0 = blockIdx.y * 32;
    const float* s = src + (size_t)b * LSEQ * DIM;
    __half* hb = hi + (size_t)b * LSEQ * DIM;
    __half* lb = lo + (size_t)b * LSEQ * DIM;
    #pragma unroll
    for (int i = 0; i < 32; i += 8) {
        float v = s[(size_t)(l0 + threadIdx.y + i) * DIM + d0 + threadIdx.x];
        t[threadIdx.y + i][threadIdx.x] = v;
        __half h, l;
        split1(v, h, l);
        size_t o = (size_t)(l0 + threadIdx.y + i) * DIM + d0 + threadIdx.x;
        hb[o] = h;
        lb[o] = l;
    }
    __syncthreads();
    size_t ob = (size_t)b * DIM * LSEQ;
    #pragma unroll
    for (int i = 0; i < 32; i += 8) {
        float v = t[threadIdx.x][threadIdx.y + i];
        hiT[ob + (size_t)(d0 + threadIdx.y + i) * LSEQ + l0 + threadIdx.x] =
            __float2half(v);
    }
}

// W transpose + split
__global__ void transpose_split(const float* __restrict__ src,
                                __half* __restrict__ hiT,
                                __half* __restrict__ loT,
                                int rows, int cols) {
    __shared__ float t[32][33];
    int r0 = blockIdx.x * 32, c0 = blockIdx.y * 32;
    #pragma unroll
    for (int i = 0; i < 32; i += 8)
        t[threadIdx.y + i][threadIdx.x] =
            src[(size_t)(r0 + threadIdx.y + i) * cols + c0 + threadIdx.x];
    __syncthreads();
    #pragma unroll
    for (int i = 0; i < 32; i += 8) {
        float v = t[threadIdx.x][threadIdx.y + i];
        __half h, l;
        split1(v, h, l);
        size_t o = (size_t)(c0 + threadIdx.y + i) * rows + r0 + threadIdx.x;
        hiT[o] = h;
        if (loT) loT[o] = l;
    }
}

// combine 8 fp32 split-K partials of M -> fp16 hi/lo
__global__ void combine_m(const float* __restrict__ parts,
                          __half* __restrict__ hi, __half* __restrict__ lo) {
    size_t i = ((size_t)blockIdx.x * blockDim.x + threadIdx.x) * 4;
    const size_t stride = (size_t)DIM * DIM;
    float s0 = 0.f, s1 = 0.f, s2 = 0.f, s3 = 0.f;
    #pragma unroll
    for (int k = 0; k < 8; ++k) {
        float4 v = *(const float4*)(parts + k * stride + i);
        s0 += v.x; s1 += v.y; s2 += v.z; s3 += v.w;
    }
    __half h0, h1, h2, h3, l0, l1, l2, l3;
    split1(s0, h0, l0); split1(s1, h1, l1);
    split1(s2, h2, l2); split1(s3, h3, l3);
    *(__half2*)(hi + i)     = __halves2half2(h0, h1);
    *(__half2*)(hi + i + 2) = __halves2half2(h2, h3);
    *(__half2*)(lo + i)     = __halves2half2(l0, l1);
    *(__half2*)(lo + i + 2) = __halves2half2(l2, l3);
}

// p[i] = sum_k b[k] * W[k,i]
__global__ void compute_p(const float* __restrict__ W,
                          const float* __restrict__ b,
                          float* __restrict__ p) {
    int i = blockIdx.x * 128 + threadIdx.x;
    float acc = 0.f;
    for (int k = 0; k < DIM; ++k)
        acc += b[k] * W[(size_t)k * DIM + i];
    p[i] = acc;
}

// r[row] = io[row,:]·p
__global__ void compute_r(const float* __restrict__ io,
                          const float* __restrict__ p,
                          float* __restrict__ r) {
    int row  = blockIdx.x * 8 + (threadIdx.x >> 5);
    int lane = threadIdx.x & 31;
    const float* src = io + (size_t)row * DIM;
    float acc = 0.f;
    for (int d = lane * 4; d < DIM; d += 128) {
        float4 v  = *(const float4*)(src + d);
        float4 pv = *(const float4*)(p + d);
        acc += v.x * pv.x + v.y * pv.y + v.z * pv.z + v.w * pv.w;
    }
    #pragma unroll
    for (int o = 16; o; o >>= 1)
        acc += __shfl_xor_sync(0xFFFFFFFFu, acc, o);
    if (lane == 0) r[row] = acc;
}

// Single-pass register-resident softmax of (S[row,:] + r[b,:]) -> P fp16.
// cols = 2048, 256 threads/row: each thread holds exactly 2 float4 (8 vals).
__global__ void softmax_h(const float* __restrict__ S,
                          const float* __restrict__ r,
                          __half* __restrict__ phi, int cols) {
    const float* row = S + (size_t)blockIdx.x * cols;
    const float* rr = r + (size_t)(blockIdx.x / LSEQ) * LSEQ;
    __half* hr = phi + (size_t)blockIdx.x * cols;
    const int tid = threadIdx.x;

    float4 v[2];
    float lmax = -3.0e38f;
    #pragma unroll
    for (int j = 0; j < 2; ++j) {
        int i = tid * 4 + j * 1024;
        v[j] = *(const float4*)(row + i);
        float4 a = *(const float4*)(rr + i);
        v[j].x += a.x; v[j].y += a.y; v[j].z += a.z; v[j].w += a.w;
        lmax = fmaxf(lmax, fmaxf(fmaxf(v[j].x, v[j].y), fmaxf(v[j].z, v[j].w)));
    }
    #pragma unroll
    for (int o = 16; o; o >>= 1)
        lmax = fmaxf(lmax, __shfl_xor_sync(0xFFFFFFFFu, lmax, o));
    __shared__ float sm[8], ss[8];
    if ((tid & 31) == 0) sm[tid >> 5] = lmax;
    __syncthreads();
    float rmax = fmaxf(fmaxf(fmaxf(sm[0], sm[1]), fmaxf(sm[2], sm[3])),
                       fmaxf(fmaxf(sm[4], sm[5]), fmaxf(sm[6], sm[7])));

    float lsum = 0.f;
    #pragma unroll
    for (int j = 0; j < 2; ++j) {
        v[j].x = expf(v[j].x - rmax); v[j].y = expf(v[j].y - rmax);
        v[j].z = expf(v[j].z - rmax); v[j].w = expf(v[j].w - rmax);
        lsum += v[j].x + v[j].y + v[j].z + v[j].w;
    }
    #pragma unroll
    for (int o = 16; o; o >>= 1)
        lsum += __shfl_xor_sync(0xFFFFFFFFu, lsum, o);
    if ((tid & 31) == 0) ss[tid >> 5] = lsum;
    __syncthreads();
    float inv = 1.f / (ss[0]+ss[1]+ss[2]+ss[3]+ss[4]+ss[5]+ss[6]+ss[7]);

    #pragma unroll
    for (int j = 0; j < 2; ++j) {
        int i = tid * 4 + j * 1024;
        __half h0 = __float2half(v[j].x * inv);
        __half h1 = __float2half(v[j].y * inv);
        __half h2 = __float2half(v[j].z * inv);
        __half h3 = __float2half(v[j].w * inv);
        *(__half2*)(hr + i)     = __halves2half2(h0, h1);
        *(__half2*)(hr + i + 2) = __halves2half2(h2, h3);
    }
}

// ============================================================================
// Split-precision HMMA GEMM (proven config), CTA 128x128, warp 64x32,
// K-chunk 32, 3 smem stages, 2 CTAs/SM. lda/ldb in elements.
// NPASS=3: C = Ah*Bh + Ah*Bl + Al*Bh.   NPASS=1: C = Ah*Bh.
// ============================================================================
#define BKC 32
#define TILE_B 8192

template<int NPASS>
__global__ __launch_bounds__(256, 2)
void gemm_split(const __half* __restrict__ Ahi, const __half* __restrict__ Alo,
                const __half* __restrict__ Bhi, const __half* __restrict__ Blo,
                float* __restrict__ Cf,
                __half* __restrict__ Chi, __half* __restrict__ Clo,
                int K, int N, int lda, int ldb,
                long long sA, long long sB, long long sC)
{
    constexpr int NT = (NPASS == 3) ? 4 : 2;
    constexpr int STAGE_B = NT * TILE_B;
    constexpr int NSTAGE = 3;

    extern __shared__ __align__(128) char smem[];
    const uint32_t sb = smem_u32(smem);

    const int tid  = threadIdx.x;
    const int wid  = tid >> 5;
    const int lane = tid & 31;
    const int wm   = wid >> 2;
    const int wn   = wid & 3;

    const long long bz = blockIdx.z;
    const long long m0 = (long long)blockIdx.y * 128;
    const long long n0 = (long long)blockIdx.x * 128;

    const __half* srcs[4];
    int lds[4];
    srcs[0] = Ahi + bz * sA + m0 * lda; lds[0] = lda;
    if (NPASS == 3) {
        srcs[1] = Alo + bz * sA + m0 * lda; lds[1] = lda;
        srcs[2] = Bhi + bz * sB + n0 * ldb; lds[2] = ldb;
        srcs[3] = Blo + bz * sB + n0 * ldb; lds[3] = ldb;
    } else {
        srcs[1] = Bhi + bz * sB + n0 * ldb; lds[1] = ldb;
        srcs[2] = nullptr; lds[2] = 0;
        srcs[3] = nullptr; lds[3] = 0;
    }

    auto load_chunk = [&](int stage, int k0) {
        const uint32_t base = sb + stage * STAGE_B;
        #pragma unroll
        for (int t = 0; t < NT; ++t) {
            #pragma unroll
            for (int j = 0; j < 2; ++j) {
                int idx = tid * 2 + j;
                int row = idx >> 2;
                int ch  = idx & 3;
                cp16(tile_addr(base + t * TILE_B, row, ch),
                     srcs[t] + (long long)row * lds[t] + k0 + ch * 8);
            }
        }
        CP_COMMIT();
    };

    float acc[4][4][4];
    #pragma unroll
    for (int i = 0; i < 4; ++i)
        #pragma unroll
        for (int j = 0; j < 4; ++j)
            #pragma unroll
            for (int e = 0; e < 4; ++e) acc[i][j][e] = 0.f;

    const int NC = K >> 5;
    load_chunk(0, 0);
    load_chunk(1, BKC);

    const int lrow = lane & 15;
    const int lch  = lane >> 4;

    for (int c = 0; c < NC; ++c) {
        if (c + 1 < NC) CP_WAIT(1); else CP_WAIT(0);
        __syncthreads();
        if (c + 2 < NC) load_chunk((c + 2) % NSTAGE, (c + 2) * BKC);

        const uint32_t st  = sb + (c % NSTAGE) * STAGE_B;
        const uint32_t sAh = st;
        const uint32_t sAl = st + TILE_B;
        const uint32_t sBh = st + ((NPASS == 3) ? 2 : 1) * TILE_B;
        const uint32_t sBl = st + 3 * TILE_B;

        #pragma unroll
        for (int ks = 0; ks < 2; ++ks) {
            const int chunk = ks * 2 + lch;
            uint32_t ahi[4][4], alo[4][4];
            uint32_t bhi[4][2], blo[4][2];

            #pragma unroll
            for (int mi = 0; mi < 4; ++mi) {
                const int row = wm * 64 + mi * 16 + lrow;
                ldsm4(ahi[mi], tile_addr(sAh, row, chunk));
                if (NPASS == 3)
                    ldsm4(alo[mi], tile_addr(sAl, row, chunk));
            }
            #pragma unroll
            for (int bi = 0; bi < 2; ++bi) {
                const int row = wn * 32 + bi * 16 + lrow;
                uint32_t t4[4];
                ldsm4(t4, tile_addr(sBh, row, chunk));
                bhi[bi*2][0]   = t4[0]; bhi[bi*2][1]   = t4[2];
                bhi[bi*2+1][0] = t4[1]; bhi[bi*2+1][1] = t4[3];
                if (NPASS == 3) {
                    ldsm4(t4, tile_addr(sBl, row, chunk));
                    blo[bi*2][0]   = t4[0]; blo[bi*2][1]   = t4[2];
                    blo[bi*2+1][0] = t4[1]; blo[bi*2+1][1] = t4[3];
                }
            }

            #pragma unroll
            for (int mi = 0; mi < 4; ++mi)
                #pragma unroll
                for (int ni = 0; ni < 4; ++ni) {
                    mma16816(acc[mi][ni], ahi[mi], bhi[ni]);
                    if (NPASS == 3) {
                        mma16816(acc[mi][ni], ahi[mi], blo[ni]);
                        mma16816(acc[mi][ni], alo[mi], bhi[ni]);
                    }
                }
        }
        __syncthreads();
    }

    // ---- epilogue ----
    const int r1 = lane >> 2;
    const int c0 = (lane & 3) * 2;
    #pragma unroll
    for (int mi = 0; mi < 4; ++mi) {
        #pragma unroll
        for (int ni = 0; ni < 4; ++ni) {
            const long long gm = m0 + wm * 64 + mi * 16 + r1;
            const long long gn = n0 + wn * 32 + ni * 8 + c0;
            float v0 = acc[mi][ni][0], v1 = acc[mi][ni][1];
            float v2 = acc[mi][ni][2], v3 = acc[mi][ni][3];
            if (Cf) {
                float* d0 = Cf + bz * sC + gm * N + gn;
                float* d1 = Cf + bz * sC + (gm + 8) * N + gn;
                d0[0] = v0; d0[1] = v1;
                d1[0] = v2; d1[1] = v3;
            } else {
                __half h0, h1, h2, h3, l0, l1, l2, l3;
                split1(v0, h0, l0); split1(v1, h1, l1);
                split1(v2, h2, l2); split1(v3, h3, l3);
                *(__half2*)(Chi + bz * sC + gm * N + gn)       = __halves2half2(h0, h1);
                *(__half2*)(Clo + bz * sC + gm * N + gn)       = __halves2half2(l0, l1);
                *(__half2*)(Chi + bz * sC + (gm + 8) * N + gn) = __halves2half2(h2, h3);
                *(__half2*)(Clo + bz * sC + (gm + 8) * N + gn) = __halves2half2(l2, l3);
            }
        }
    }
}

// ============================================================================
extern "C" void kernel_launch(void* const* d_in, const int* in_sizes, int n_in,
                              void* d_out, int out_size)
{
    const float* ix = (const float*)d_in[0];
    const float* io = (const float*)d_in[1];
    const float* W  = (const float*)d_in[2];
    const float* bb = (const float*)d_in[3];
    float* out = (float*)d_out;

    __half *ix_hi, *ix_lo, *io_hi, *io_lo, *ioT_hi;
    __half *t_hi, *t_lo, *wt_hi, *wt_lo, *m_hi, *m_lo, *p_hi;
    float *s, *pv, *rv;
    cudaGetSymbolAddress((void**)&ix_hi, g_ix_hi);
    cudaGetSymbolAddress((void**)&ix_lo, g_ix_lo);
    cudaGetSymbolAddress((void**)&io_hi, g_io_hi);
    cudaGetSymbolAddress((void**)&io_lo, g_io_lo);
    cudaGetSymbolAddress((void**)&ioT_hi, g_ioT_hi);
    cudaGetSymbolAddress((void**)&t_hi, g_t_hi);
    cudaGetSymbolAddress((void**)&t_lo, g_t_lo);
    cudaGetSymbolAddress((void**)&wt_hi, g_wt_hi);
    cudaGetSymbolAddress((void**)&wt_lo, g_wt_lo);
    cudaGetSymbolAddress((void**)&m_hi, g_m_hi);
    cudaGetSymbolAddress((void**)&m_lo, g_m_lo);
    cudaGetSymbolAddress((void**)&p_hi, g_p_hi);
    cudaGetSymbolAddress((void**)&s, g_s);
    cudaGetSymbolAddress((void**)&pv, g_p_vec);
    cudaGetSymbolAddress((void**)&rv, g_r);

    static bool init_done = false;
    static cudaStream_t s1, s2;
    static cudaEvent_t ev_fork, ev_ix, ev_io, ev_r, ev_t;
    static cudaEvent_t ev_sc0, ev_sc1, ev_sm0, ev_sm1, ev_join;
    const int smem3 = 3 * 4 * TILE_B;   // 96 KB
    const int smem1 = 3 * 2 * TILE_B;   // 48 KB
    if (!init_done) {
        cudaFuncSetAttribute(gemm_split<3>,
                             cudaFuncAttributeMaxDynamicSharedMemorySize, smem3);
        cudaFuncSetAttribute(gemm_split<1>,
                             cudaFuncAttributeMaxDynamicSharedMemorySize, smem1);
        cudaStreamCreateWithFlags(&s1, cudaStreamNonBlocking);
        cudaStreamCreateWithFlags(&s2, cudaStreamNonBlocking);
        cudaEventCreateWithFlags(&ev_fork, cudaEventDisableTiming);
        cudaEventCreateWithFlags(&ev_ix,   cudaEventDisableTiming);
        cudaEventCreateWithFlags(&ev_io,   cudaEventDisableTiming);
        cudaEventCreateWithFlags(&ev_r,    cudaEventDisableTiming);
        cudaEventCreateWithFlags(&ev_t,    cudaEventDisableTiming);
        cudaEventCreateWithFlags(&ev_sc0,  cudaEventDisableTiming);
        cudaEventCreateWithFlags(&ev_sc1,  cudaEventDisableTiming);
        cudaEventCreateWithFlags(&ev_sm0,  cudaEventDisableTiming);
        cudaEventCreateWithFlags(&ev_sm1,  cudaEventDisableTiming);
        cudaEventCreateWithFlags(&ev_join, cudaEventDisableTiming);
        init_done = true;
    }

    // ---- fork side streams ----
    cudaEventRecord(ev_fork, 0);
    cudaStreamWaitEvent(s1, ev_fork, 0);
    cudaStreamWaitEvent(s2, ev_fork, 0);

    // s1: prep kernels (overlap with M/t GEMMs on stream 0)
    split_f32<<<(unsigned)(MELEMS / 4 / 256), 256, 0, s1>>>(ix, ix_hi, ix_lo, MELEMS);
    cudaEventRecord(ev_ix, s1);
    prep_io<<<dim3(LSEQ / 32, DIM / 32, BATCH), dim3(32, 8), 0, s1>>>(
        io, io_hi, io_lo, ioT_hi);
    cudaEventRecord(ev_io, s1);
    compute_p<<<DIM / 128, 128, 0, s1>>>(W, bb, pv);
    compute_r<<<(BATCH * LSEQ) / 8, 256, 0, s1>>>(io, pv, rv);
    cudaEventRecord(ev_r, s1);

    // ---- stream 0: head ----
    transpose_split<<<dim3(DIM / 32, DIM / 32, 1), dim3(32, 8)>>>(
        W, wt_hi, wt_lo, DIM, DIM);

    // M = W^T W, split-K x8, then combine
    {
        dim3 g(DIM / 128, DIM / 128, 8);
        gemm_split<3><<<g, 256, smem3>>>(wt_hi, wt_lo, wt_hi, wt_lo,
                                         s, nullptr, nullptr,
                                         DIM / 8, DIM, DIM, DIM,
                                         DIM / 8, DIM / 8,
                                         (long long)DIM * DIM);
        combine_m<<<(DIM * DIM) / 4 / 256, 256>>>(s, m_hi, m_lo);
    }

    // t = ix @ M (symmetric), 3-pass -> fp16 split
    cudaStreamWaitEvent(0, ev_ix, 0);
    {
        dim3 g(DIM / 128, (BATCH * LSEQ) / 128, 1);
        gemm_split<3><<<g, 256, smem3>>>(ix_hi, ix_lo, m_hi, m_lo,
                                         nullptr, t_hi, t_lo,
                                         DIM, DIM, DIM, DIM, 0, 0, 0);
    }
    cudaEventRecord(ev_t, 0);

    // ---- scores halves: b0-3 on stream 0, b4-7 on s2 (concurrent) ----
    cudaStreamWaitEvent(0,  ev_io, 0);
    cudaStreamWaitEvent(s2, ev_io, 0);
    cudaStreamWaitEvent(s2, ev_t, 0);
    {
        dim3 g(LSEQ / 128, LSEQ / 128, HB);
        gemm_split<3><<<g, 256, smem3>>>(t_hi, t_lo, io_hi, io_lo,
                                         s, nullptr, nullptr,
                                         DIM, LSEQ, DIM, DIM,
                                         (long long)LSEQ * DIM,
                                         (long long)LSEQ * DIM,
                                         (long long)LSEQ * LSEQ);
        cudaEventRecord(ev_sc0, 0);

        const size_t off = (size_t)HB * LSEQ * DIM;
        const size_t offS = (size_t)HB * LSEQ * LSEQ;
        gemm_split<3><<<g, 256, smem3, s2>>>(t_hi + off, t_lo + off,
                                             io_hi + off, io_lo + off,
                                             s + offS, nullptr, nullptr,
                                             DIM, LSEQ, DIM, DIM,
                                             (long long)LSEQ * DIM,
                                             (long long)LSEQ * DIM,
                                             (long long)LSEQ * LSEQ);
        cudaEventRecord(ev_sc1, s2);
    }

    // ---- softmax halves on s1 (hidden under remaining score waves) ----
    cudaStreamWaitEvent(s1, ev_sc0, 0);   // s1 already ordered after ev_r
    softmax_h<<<HB * LSEQ, 256, 0, s1>>>(s, rv, p_hi, LSEQ);
    cudaEventRecord(ev_sm0, s1);
    cudaStreamWaitEvent(s1, ev_sc1, 0);
    softmax_h<<<HB * LSEQ, 256, 0, s1>>>(
        s + (size_t)HB * LSEQ * LSEQ, rv + (size_t)HB * LSEQ,
        p_hi + (size_t)HB * LSEQ * LSEQ, LSEQ);
    cudaEventRecord(ev_sm1, s1);

    // ---- out halves: b0-3 on stream 0, b4-7 on s2 ----
    cudaStreamWaitEvent(0, ev_sm0, 0);
    {
        dim3 g(DIM / 128, LSEQ / 128, HB);
        gemm_split<1><<<g, 256, smem1>>>(p_hi, nullptr, ioT_hi, nullptr,
                                         out, nullptr, nullptr,
                                         LSEQ, DIM, LSEQ, LSEQ,
                                         (long long)LSEQ * LSEQ,
                                         (long long)DIM * LSEQ,
                                         (long long)LSEQ * DIM);

        cudaStreamWaitEvent(s2, ev_sm1, 0);
        gemm_split<1><<<g, 256, smem1, s2>>>(
            p_hi + (size_t)HB * LSEQ * LSEQ, nullptr,
            ioT_hi + (size_t)HB * DIM * LSEQ, nullptr,
            out + (size_t)HB * LSEQ * DIM, nullptr, nullptr,
            LSEQ, DIM, LSEQ, LSEQ,
            (long long)LSEQ * LSEQ,
            (long long)DIM * LSEQ,
            (long long)LSEQ * DIM);
    }

    // join s2 back into stream 0
    cudaEventRecord(ev_join, s2);
    cudaStreamWaitEvent(0, ev_join, 0);
}